// round 2
// baseline (speedup 1.0000x reference)
#include <cuda_runtime.h>
#include <math.h>

// Problem constants
#define BATCH 8
#define C     192
#define HH    224
#define WW    224
#define P     7
#define PP    49          // tokens per window
#define NH    6
#define HD    32
#define NWX   32          // windows per row
#define NW    1024        // windows per image
#define C3    576         // 3*C
#define NT    576         // threads per block

// Prep scratch (static __device__ globals are the allowed scratch mechanism)
__device__ float g_wqkvT[C * C3];        // [k][j]  transposed qkv weight
__device__ float g_woutT[C * C];         // [k][j]  transposed out weight
__device__ float g_bias[NH * PP * PP];   // [h][p][q] expanded relative bias

// ---------------------------------------------------------------------------
// Prep: transpose weights for coalesced column loads; expand rel-pos bias.
// ---------------------------------------------------------------------------
__global__ void prep_kernel(const float* __restrict__ w_qkv,
                            const float* __restrict__ w_out,
                            const float* __restrict__ rel_pos) {
    int tid = blockIdx.x * blockDim.x + threadIdx.x;
    int stride = gridDim.x * blockDim.x;
    for (int i = tid; i < C3 * C; i += stride) {
        int j = i / C, k = i % C;
        g_wqkvT[k * C3 + j] = w_qkv[i];
    }
    for (int i = tid; i < C * C; i += stride) {
        int j = i / C, k = i % C;
        g_woutT[k * C + j] = w_out[i];
    }
    for (int i = tid; i < NH * PP * PP; i += stride) {
        int h = i / (PP * PP);
        int rem = i % (PP * PP);
        int p = rem / PP, q = rem % PP;
        int ri = (p / P) - (q / P) + P - 1;
        int rj = (p % P) - (q % P) + P - 1;
        g_bias[i] = rel_pos[(h * (2 * P - 1) + ri) * (2 * P - 1) + rj];
    }
}

// ---------------------------------------------------------------------------
// Fused window attention: one CTA per window.
// smem layout (floats):
//   xs    : 49 x 193 (stride 193 padding -> conflict-free row/col access)
//           (reused later as the attention output buffer, 49 x 192 used)
//   qs,ks,vs : 49 x 192 each
//   probs : 294 x 49   (reused later as res, 49 x 193)
// ---------------------------------------------------------------------------
#define XS_STRIDE 193
#define SMEM_FLOATS (PP * XS_STRIDE + 3 * PP * C + NH * PP * PP)
#define SMEM_BYTES  (SMEM_FLOATS * 4)

__global__ void __launch_bounds__(NT, 1)
win_attn_kernel(const float* __restrict__ x,
                const float* __restrict__ b_qkv,
                const float* __restrict__ b_out,
                float* __restrict__ out) {
    extern __shared__ float smem[];
    float* xs    = smem;                    // [t][ch], stride 193
    float* qs    = xs + PP * XS_STRIDE;     // [t][j],  stride 192
    float* ks    = qs + PP * C;
    float* vs    = ks + PP * C;
    float* probs = vs + PP * C;             // [h*49+p][q]
    float* res   = probs;                   // reuse: [t][ch], stride 193

    const int bx    = blockIdx.x;
    const int batch = bx / NW;
    const int win   = bx % NW;
    const int wy    = win / NWX;
    const int wx    = win % NWX;
    const int tid   = threadIdx.x;

    // ---- phase 1: load window into smem (global reads 7-contiguous) ----
    const float* xbase = x + (size_t)batch * C * HH * WW
                           + (size_t)(wy * P) * WW + (wx * P);
    for (int i = tid; i < PP * C; i += NT) {
        int t  = i % PP;
        int ch = i / PP;
        int pi = t / P, pj = t % P;
        xs[t * XS_STRIDE + ch] = xbase[((size_t)ch * HH + pi) * WW + pj];
    }
    __syncthreads();

    // ---- phase 2: QKV GEMM, one output column per thread ----
    {
        const int j = tid;  // 0..575
        float acc[PP];
#pragma unroll
        for (int r = 0; r < PP; r++) acc[r] = 0.f;
        const float* wp = g_wqkvT + j;
        for (int k = 0; k < C; k++) {
            float w = wp[k * C3];            // coalesced across threads
            const float* xr = xs + k;        // broadcast across warp
#pragma unroll
            for (int r = 0; r < PP; r++) acc[r] += xr[r * XS_STRIDE] * w;
        }
        float bj = b_qkv[j];
        float* dst = (j < C) ? (qs + j) : ((j < 2 * C) ? (ks + (j - C))
                                                       : (vs + (j - 2 * C)));
#pragma unroll
        for (int r = 0; r < PP; r++) dst[r * C] = acc[r] + bj;
    }
    __syncthreads();

    // ---- phase 3+4: attention (thread = (head, row)), softmax, PV ----
    if (tid < NH * PP) {
        const int h = tid / PP, p = tid % PP;
        const float scale = 0.1767766952966369f;  // 1/sqrt(32)

        float qv[HD];
#pragma unroll
        for (int d = 0; d < HD; d++) qv[d] = qs[p * C + h * HD + d];

        float* prow = probs + tid * PP;
        const float* brow = g_bias + (h * PP + p) * PP;

        float mx = -1e30f;
        for (int q = 0; q < PP; q++) {
            float acc = 0.f;
            const float* kr = ks + q * C + h * HD;  // warp-broadcast
#pragma unroll
            for (int d = 0; d < HD; d++) acc += qv[d] * kr[d];
            float s = acc * scale + brow[q];
            prow[q] = s;
            mx = fmaxf(mx, s);
        }
        float sum = 0.f;
        for (int q = 0; q < PP; q++) {
            float e = __expf(prow[q] - mx);
            prow[q] = e;
            sum += e;
        }
        float inv = 1.f / sum;
        for (int q = 0; q < PP; q++) prow[q] *= inv;

        // PV: out[p][h*32+d] = sum_q probs[q] * v[q][h*32+d]
        float acc[HD];
#pragma unroll
        for (int d = 0; d < HD; d++) acc[d] = 0.f;
        for (int q = 0; q < PP; q++) {
            float pr = prow[q];
            const float* vr = vs + q * C + h * HD;  // warp-broadcast
#pragma unroll
            for (int d = 0; d < HD; d++) acc[d] += pr * vr[d];
        }
        float* dst = xs + p * XS_STRIDE + h * HD;   // reuse xs as attn buffer
#pragma unroll
        for (int d = 0; d < HD; d++) dst[d] = acc[d];
    }
    __syncthreads();

    // ---- phase 5: output projection. 3 row-groups x 192 columns ----
    {
        const int j  = tid % C;       // column
        const int rg = tid / C;       // 0,1,2
        const int r0 = rg * 16;       // rows [r0, r0+16] (17 rows, overlapping)
        float acc[17];
#pragma unroll
        for (int r = 0; r < 17; r++) acc[r] = 0.f;
        const float* wp = g_woutT + j;
        for (int k = 0; k < C; k++) {
            float w = wp[k * C];                   // coalesced across threads
            const float* xr = xs + r0 * XS_STRIDE + k;
#pragma unroll
            for (int r = 0; r < 17; r++) acc[r] += xr[r * XS_STRIDE] * w;
        }
        float bj = b_out[j];
        int wstart = (rg == 0) ? 0 : 1;            // skip duplicated boundary rows
#pragma unroll
        for (int r = 0; r < 17; r++) {
            if (r >= wstart) res[(r0 + r) * XS_STRIDE + j] = acc[r] + bj;
        }
    }
    __syncthreads();

    // ---- phase 6: window-reverse, coalesced global write ----
    float* obase = out + (size_t)batch * C * HH * WW
                       + (size_t)(wy * P) * WW + (wx * P);
    for (int i = tid; i < PP * C; i += NT) {
        int t  = i % PP;
        int ch = i / PP;
        int pi = t / P, pj = t % P;
        obase[((size_t)ch * HH + pi) * WW + pj] = res[t * XS_STRIDE + ch];
    }
}

// ---------------------------------------------------------------------------
extern "C" void kernel_launch(void* const* d_in, const int* in_sizes, int n_in,
                              void* d_out, int out_size) {
    const float* x       = (const float*)d_in[0];
    const float* w_qkv   = (const float*)d_in[1];
    const float* b_qkv   = (const float*)d_in[2];
    const float* rel_pos = (const float*)d_in[3];
    const float* w_out   = (const float*)d_in[4];
    const float* b_out   = (const float*)d_in[5];
    float* out           = (float*)d_out;

    prep_kernel<<<96, 256>>>(w_qkv, w_out, rel_pos);

    cudaFuncSetAttribute(win_attn_kernel,
                         cudaFuncAttributeMaxDynamicSharedMemorySize,
                         SMEM_BYTES);
    win_attn_kernel<<<BATCH * NW, NT, SMEM_BYTES>>>(x, b_qkv, b_out, out);
}

// round 4
// speedup vs baseline: 1.4997x; 1.4997x over previous
#include <cuda_runtime.h>
#include <cstdint>

// Problem constants
#define BATCH 8
#define C     192
#define HH    224
#define WW    224
#define P     7
#define PP    49          // tokens per window
#define NH    6
#define HD    32
#define NWX   32
#define NW    1024
#define C3    576
#define NT    576
#define TS    52          // transposed tile stride (floats), %4==0 for LDS.128
#define RS    49          // result-tile stride (odd -> conflict-free scalar access)

// Prep scratch
__device__ float g_wqkvT[C * C3];        // [k][j]
__device__ float g_woutT[C * C];         // [k][j]
__device__ float g_bias[NH * PP * PP];   // [h][p][q]

// ---------------------------------------------------------------------------
__global__ void prep_kernel(const float* __restrict__ w_qkv,
                            const float* __restrict__ w_out,
                            const float* __restrict__ rel_pos) {
    int tid = blockIdx.x * blockDim.x + threadIdx.x;
    int stride = gridDim.x * blockDim.x;
    for (int i = tid; i < C3 * C; i += stride) {
        int j = i / C, k = i % C;
        g_wqkvT[k * C3 + j] = w_qkv[i];
    }
    for (int i = tid; i < C * C; i += stride) {
        int j = i / C, k = i % C;
        g_woutT[k * C + j] = w_out[i];
    }
    for (int i = tid; i < NH * PP * PP; i += stride) {
        int h = i / (PP * PP);
        int rem = i % (PP * PP);
        int p = rem / PP, q = rem % PP;
        int ri = (p / P) - (q / P) + P - 1;
        int rj = (p % P) - (q % P) + P - 1;
        g_bias[i] = rel_pos[(h * (2 * P - 1) + ri) * (2 * P - 1) + rj];
    }
}

// ---------------------------------------------------------------------------
// Packed fp32x2 helpers (sm_100+ f32x2 pipe; ptxas never auto-fuses these)
// ---------------------------------------------------------------------------
__device__ __forceinline__ unsigned long long pack2(float a, float b) {
    unsigned long long r;
    asm("mov.b64 %0, {%1, %2};" : "=l"(r) : "f"(a), "f"(b));
    return r;
}
__device__ __forceinline__ void unpack2(unsigned long long v, float& a, float& b) {
    asm("mov.b64 {%0, %1}, %2;" : "=f"(a), "=f"(b) : "l"(v));
}
__device__ __forceinline__ void ffma2(unsigned long long& d,
                                      unsigned long long a,
                                      unsigned long long b) {
    asm("fma.rn.f32x2 %0, %1, %2, %0;" : "+l"(d) : "l"(a), "l"(b));
}

// ---------------------------------------------------------------------------
// smem layout (floats):
//   xsT  : 192 x 52  [ch][t]   (phases 1-2; reused as aT, the attn output, 4-5)
//   qkv  : 49 x 576  [t][j]    (phases 2-4; reused as resT 192 x 49, 5-6)
//   probs: 294 x 49  [h*49+p][q]
// ---------------------------------------------------------------------------
#define SMEM_FLOATS (C * TS + PP * C3 + NH * PP * PP)
#define SMEM_BYTES  (SMEM_FLOATS * 4)

__global__ void __launch_bounds__(NT, 1)
win_attn_kernel(const float* __restrict__ x,
                const float* __restrict__ b_qkv,
                const float* __restrict__ b_out,
                float* __restrict__ out) {
    extern __shared__ float smem[];
    float* xsT   = smem;                 // [ch][t] stride TS ; later aT
    float* qkv   = smem + C * TS;        // [t][j]  stride C3 ; later resT (stride RS)
    float* probs = qkv + PP * C3;        // [tid][q] stride RS

    const int bx    = blockIdx.x;
    const int batch = bx / NW;
    const int win   = bx % NW;
    const int wy    = win / NWX;
    const int wx    = win % NWX;
    const int tid   = threadIdx.x;

    // ---- phase 1: load window, transposed into smem ----
    const float* xbase = x + (size_t)batch * C * HH * WW
                           + (size_t)(wy * P) * WW + (wx * P);
    for (int i = tid; i < PP * C; i += NT) {
        int t  = i % PP;
        int ch = i / PP;
        int pi = t / P, pj = t % P;
        xsT[ch * TS + t] = xbase[((size_t)ch * HH + pi) * WW + pj];
    }
    __syncthreads();

    // ---- phase 2: QKV GEMM, 1 column/thread, rows packed 2-wide ----
    {
        const int j = tid;  // 0..575
        unsigned long long acc[24];
        float acc48 = 0.f;
#pragma unroll
        for (int i = 0; i < 24; i++) acc[i] = 0ULL;
        const float* wp = g_wqkvT + j;
        for (int k = 0; k < C; k++) {
            float w = wp[k * C3];                         // coalesced LDG
            unsigned long long ww = pack2(w, w);
            const ulonglong2* xr = (const ulonglong2*)(xsT + k * TS);
#pragma unroll
            for (int i = 0; i < 12; i++) {               // 12 x LDS.128 = rows 0..47
                ulonglong2 v = xr[i];
                ffma2(acc[2 * i],     v.x, ww);
                ffma2(acc[2 * i + 1], v.y, ww);
            }
            acc48 = fmaf(xsT[k * TS + 48], w, acc48);
        }
        float bj = b_qkv[j];
        float* dst = qkv + j;
#pragma unroll
        for (int i = 0; i < 24; i++) {
            float a, b;
            unpack2(acc[i], a, b);
            dst[(2 * i) * C3]     = a + bj;
            dst[(2 * i + 1) * C3] = b + bj;
        }
        dst[48 * C3] = acc48 + bj;
    }
    __syncthreads();

    // ---- phase 3+4: attention. thread = (head, row). packed dot products ----
    float* aT = xsT;  // reuse (xsT dead after phase 2)
    if (tid < NH * PP) {
        const int h = tid / PP, p = tid % PP;
        const float scale = 0.1767766952966369f;  // 1/sqrt(32)

        unsigned long long qv[16];
        {
            const ulonglong2* qp = (const ulonglong2*)(qkv + p * C3 + h * HD);
#pragma unroll
            for (int i = 0; i < 8; i++) {
                ulonglong2 v = qp[i];
                qv[2 * i] = v.x; qv[2 * i + 1] = v.y;
            }
        }

        float* prow = probs + tid * RS;
        const float* brow = g_bias + (h * PP + p) * PP;

        float mx = -1e30f;
        for (int q = 0; q < PP; q++) {
            const ulonglong2* kp = (const ulonglong2*)(qkv + q * C3 + C + h * HD);
            unsigned long long a0 = 0ULL, a1 = 0ULL;
#pragma unroll
            for (int i = 0; i < 8; i++) {
                ulonglong2 v = kp[i];
                ffma2(a0, qv[2 * i],     v.x);
                ffma2(a1, qv[2 * i + 1], v.y);
            }
            float s0, s1, s2, s3;
            unpack2(a0, s0, s1);
            unpack2(a1, s2, s3);
            float s = ((s0 + s1) + (s2 + s3)) * scale + brow[q];
            prow[q] = s;
            mx = fmaxf(mx, s);
        }
        float sum = 0.f;
        for (int q = 0; q < PP; q++) {
            float e = __expf(prow[q] - mx);
            prow[q] = e;
            sum += e;
        }
        float inv = 1.f / sum;

        // PV, packed: acc[d/2] over 32 dims
        unsigned long long acc[16];
#pragma unroll
        for (int i = 0; i < 16; i++) acc[i] = 0ULL;
        for (int q = 0; q < PP; q++) {
            float pr = prow[q] * inv;
            unsigned long long pp2 = pack2(pr, pr);
            const ulonglong2* vp = (const ulonglong2*)(qkv + q * C3 + 2 * C + h * HD);
#pragma unroll
            for (int i = 0; i < 8; i++) {
                ulonglong2 v = vp[i];
                ffma2(acc[2 * i],     v.x, pp2);
                ffma2(acc[2 * i + 1], v.y, pp2);
            }
        }
        // store transposed: aT[(h*32+d)][p]
#pragma unroll
        for (int i = 0; i < 16; i++) {
            float a, b;
            unpack2(acc[i], a, b);
            aT[(h * HD + 2 * i) * TS + p]     = a;
            aT[(h * HD + 2 * i + 1) * TS + p] = b;
        }
    }
    __syncthreads();

    // ---- phase 5: output projection, packed rows ----
    float* resT = qkv;  // reuse (q/k/v dead), layout [ch][t] stride RS
    {
        const int j  = tid % C;
        const int rg = tid / C;       // 0,1,2
        const int r0 = rg * 16;       // rows [r0, r0+16], boundary rows duplicated
        unsigned long long acc[8];
        float acc16 = 0.f;
#pragma unroll
        for (int i = 0; i < 8; i++) acc[i] = 0ULL;
        const float* wp = g_woutT + j;
        for (int k = 0; k < C; k++) {
            float w = wp[k * C];
            unsigned long long ww = pack2(w, w);
            const ulonglong2* xr = (const ulonglong2*)(aT + k * TS + r0);
#pragma unroll
            for (int i = 0; i < 4; i++) {
                ulonglong2 v = xr[i];
                ffma2(acc[2 * i],     v.x, ww);
                ffma2(acc[2 * i + 1], v.y, ww);
            }
            acc16 = fmaf(aT[k * TS + r0 + 16], w, acc16);
        }
        float bj = b_out[j];
#pragma unroll
        for (int i = 0; i < 8; i++) {
            float a, b;
            unpack2(acc[i], a, b);
            resT[j * RS + r0 + 2 * i]     = a + bj;   // duplicated boundary rows
            resT[j * RS + r0 + 2 * i + 1] = b + bj;   // write identical bits: benign
        }
        resT[j * RS + r0 + 16] = acc16 + bj;
    }
    __syncthreads();

    // ---- phase 6: window-reverse, coalesced write ----
    float* obase = out + (size_t)batch * C * HH * WW
                       + (size_t)(wy * P) * WW + (wx * P);
    for (int i = tid; i < PP * C; i += NT) {
        int t  = i % PP;
        int ch = i / PP;
        int pi = t / P, pj = t % P;
        obase[((size_t)ch * HH + pi) * WW + pj] = resT[ch * RS + t];
    }
}

// ---------------------------------------------------------------------------
extern "C" void kernel_launch(void* const* d_in, const int* in_sizes, int n_in,
                              void* d_out, int out_size) {
    const float* x       = (const float*)d_in[0];
    const float* w_qkv   = (const float*)d_in[1];
    const float* b_qkv   = (const float*)d_in[2];
    const float* rel_pos = (const float*)d_in[3];
    const float* w_out   = (const float*)d_in[4];
    const float* b_out   = (const float*)d_in[5];
    float* out           = (float*)d_out;

    prep_kernel<<<96, 256>>>(w_qkv, w_out, rel_pos);

    cudaFuncSetAttribute(win_attn_kernel,
                         cudaFuncAttributeMaxDynamicSharedMemorySize,
                         SMEM_BYTES);
    win_attn_kernel<<<BATCH * NW, NT, SMEM_BYTES>>>(x, b_qkv, b_out, out);
}

// round 6
// speedup vs baseline: 1.5008x; 1.0007x over previous
#include <cuda_runtime.h>
#include <cstdint>

// Problem constants
#define BATCH 8
#define C     192
#define HH    224
#define WW    224
#define P     7
#define PP    49          // tokens per window
#define NH    6
#define HD    32
#define NWX   32
#define NW    1024
#define C3    576
#define NT    576
#define TS    52          // transposed tile stride (floats), %4==0 for LDS.128
#define RS    49          // result-tile stride (odd -> conflict-free scalar access)

// Prep scratch
__device__ float g_wqkvT[C * C3];        // [k][j]
__device__ float g_woutT[C * C];         // [k][j]
__device__ float g_bias[NH * PP * PP];   // [h][p][q]

// ---------------------------------------------------------------------------
__global__ void prep_kernel(const float* __restrict__ w_qkv,
                            const float* __restrict__ w_out,
                            const float* __restrict__ rel_pos) {
    int tid = blockIdx.x * blockDim.x + threadIdx.x;
    int stride = gridDim.x * blockDim.x;
    for (int i = tid; i < C3 * C; i += stride) {
        int j = i / C, k = i % C;
        g_wqkvT[k * C3 + j] = w_qkv[i];
    }
    for (int i = tid; i < C * C; i += stride) {
        int j = i / C, k = i % C;
        g_woutT[k * C + j] = w_out[i];
    }
    for (int i = tid; i < NH * PP * PP; i += stride) {
        int h = i / (PP * PP);
        int rem = i % (PP * PP);
        int p = rem / PP, q = rem % PP;
        int ri = (p / P) - (q / P) + P - 1;
        int rj = (p % P) - (q % P) + P - 1;
        g_bias[i] = rel_pos[(h * (2 * P - 1) + ri) * (2 * P - 1) + rj];
    }
}

// ---------------------------------------------------------------------------
// Packed fp32x2 helpers (sm_100+ f32x2 pipe; ptxas never auto-fuses these)
// ---------------------------------------------------------------------------
__device__ __forceinline__ unsigned long long pack2(float a, float b) {
    unsigned long long r;
    asm("mov.b64 %0, {%1, %2};" : "=l"(r) : "f"(a), "f"(b));
    return r;
}
__device__ __forceinline__ void unpack2(unsigned long long v, float& a, float& b) {
    asm("mov.b64 {%0, %1}, %2;" : "=f"(a), "=f"(b) : "l"(v));
}
__device__ __forceinline__ void ffma2(unsigned long long& d,
                                      unsigned long long a,
                                      unsigned long long b) {
    asm("fma.rn.f32x2 %0, %1, %2, %0;" : "+l"(d) : "l"(a), "l"(b));
}

// ---------------------------------------------------------------------------
// smem layout (floats):
//   xsT  : 192 x 52  [ch][t]   (phases 1-2; reused as aT, the attn output, 4-5)
//   qkv  : 49 x 576  [t][j]    (phases 2-4; reused as resT 192 x 49, 5-6)
//   probs: 294 x 49  [h*49+p][q]
// ---------------------------------------------------------------------------
#define SMEM_FLOATS (C * TS + PP * C3 + NH * PP * PP)
#define SMEM_BYTES  (SMEM_FLOATS * 4)

__global__ void __launch_bounds__(NT, 1)
win_attn_kernel(const float* __restrict__ x,
                const float* __restrict__ b_qkv,
                const float* __restrict__ b_out,
                float* __restrict__ out) {
    extern __shared__ float smem[];
    float* xsT   = smem;                 // [ch][t] stride TS ; later aT
    float* qkv   = smem + C * TS;        // [t][j]  stride C3 ; later resT (stride RS)
    float* probs = qkv + PP * C3;        // [tid][q] stride RS

    const int bx    = blockIdx.x;
    const int batch = bx / NW;
    const int win   = bx % NW;
    const int wy    = win / NWX;
    const int wx    = win % NWX;
    const int tid   = threadIdx.x;

    // ---- phase 1: load window, transposed into smem ----
    const float* xbase = x + (size_t)batch * C * HH * WW
                           + (size_t)(wy * P) * WW + (wx * P);
    for (int i = tid; i < PP * C; i += NT) {
        int t  = i % PP;
        int ch = i / PP;
        int pi = t / P, pj = t % P;
        xsT[ch * TS + t] = xbase[((size_t)ch * HH + pi) * WW + pj];
    }
    __syncthreads();

    // ---- phase 2: QKV GEMM, 1 column/thread, rows packed 2-wide ----
    {
        const int j = tid;  // 0..575
        unsigned long long acc[24];
        float acc48 = 0.f;
#pragma unroll
        for (int i = 0; i < 24; i++) acc[i] = 0ULL;
        const float* wp = g_wqkvT + j;
        for (int k = 0; k < C; k++) {
            float w = wp[k * C3];                         // coalesced LDG
            unsigned long long ww = pack2(w, w);
            const ulonglong2* xr = (const ulonglong2*)(xsT + k * TS);
#pragma unroll
            for (int i = 0; i < 12; i++) {               // 12 x LDS.128 = rows 0..47
                ulonglong2 v = xr[i];
                ffma2(acc[2 * i],     v.x, ww);
                ffma2(acc[2 * i + 1], v.y, ww);
            }
            acc48 = fmaf(xsT[k * TS + 48], w, acc48);
        }
        float bj = b_qkv[j];
        float* dst = qkv + j;
#pragma unroll
        for (int i = 0; i < 24; i++) {
            float a, b;
            unpack2(acc[i], a, b);
            dst[(2 * i) * C3]     = a + bj;
            dst[(2 * i + 1) * C3] = b + bj;
        }
        dst[48 * C3] = acc48 + bj;
    }
    __syncthreads();

    // ---- phase 3+4: attention. thread = (head, row). packed dot products ----
    float* aT = xsT;  // reuse (xsT dead after phase 2)
    if (tid < NH * PP) {
        const int h = tid / PP, p = tid % PP;
        const float scale = 0.1767766952966369f;  // 1/sqrt(32)

        unsigned long long qv[16];
        {
            const ulonglong2* qp = (const ulonglong2*)(qkv + p * C3 + h * HD);
#pragma unroll
            for (int i = 0; i < 8; i++) {
                ulonglong2 v = qp[i];
                qv[2 * i] = v.x; qv[2 * i + 1] = v.y;
            }
        }

        float* prow = probs + tid * RS;
        const float* brow = g_bias + (h * PP + p) * PP;

        float mx = -1e30f;
        for (int q = 0; q < PP; q++) {
            const ulonglong2* kp = (const ulonglong2*)(qkv + q * C3 + C + h * HD);
            unsigned long long a0 = 0ULL, a1 = 0ULL;
#pragma unroll
            for (int i = 0; i < 8; i++) {
                ulonglong2 v = kp[i];
                ffma2(a0, qv[2 * i],     v.x);
                ffma2(a1, qv[2 * i + 1], v.y);
            }
            float s0, s1, s2, s3;
            unpack2(a0, s0, s1);
            unpack2(a1, s2, s3);
            float s = ((s0 + s1) + (s2 + s3)) * scale + brow[q];
            prow[q] = s;
            mx = fmaxf(mx, s);
        }
        float sum = 0.f;
        for (int q = 0; q < PP; q++) {
            float e = __expf(prow[q] - mx);
            prow[q] = e;
            sum += e;
        }
        float inv = 1.f / sum;

        // PV, packed: acc[d/2] over 32 dims
        unsigned long long acc[16];
#pragma unroll
        for (int i = 0; i < 16; i++) acc[i] = 0ULL;
        for (int q = 0; q < PP; q++) {
            float pr = prow[q] * inv;
            unsigned long long pp2 = pack2(pr, pr);
            const ulonglong2* vp = (const ulonglong2*)(qkv + q * C3 + 2 * C + h * HD);
#pragma unroll
            for (int i = 0; i < 8; i++) {
                ulonglong2 v = vp[i];
                ffma2(acc[2 * i],     v.x, pp2);
                ffma2(acc[2 * i + 1], v.y, pp2);
            }
        }
        // store transposed: aT[(h*32+d)][p]
#pragma unroll
        for (int i = 0; i < 16; i++) {
            float a, b;
            unpack2(acc[i], a, b);
            aT[(h * HD + 2 * i) * TS + p]     = a;
            aT[(h * HD + 2 * i + 1) * TS + p] = b;
        }
    }
    __syncthreads();

    // ---- phase 5: output projection, packed rows ----
    float* resT = qkv;  // reuse (q/k/v dead), layout [ch][t] stride RS
    {
        const int j  = tid % C;
        const int rg = tid / C;       // 0,1,2
        const int r0 = rg * 16;       // rows [r0, r0+16], boundary rows duplicated
        unsigned long long acc[8];
        float acc16 = 0.f;
#pragma unroll
        for (int i = 0; i < 8; i++) acc[i] = 0ULL;
        const float* wp = g_woutT + j;
        for (int k = 0; k < C; k++) {
            float w = wp[k * C];
            unsigned long long ww = pack2(w, w);
            const ulonglong2* xr = (const ulonglong2*)(aT + k * TS + r0);
#pragma unroll
            for (int i = 0; i < 4; i++) {
                ulonglong2 v = xr[i];
                ffma2(acc[2 * i],     v.x, ww);
                ffma2(acc[2 * i + 1], v.y, ww);
            }
            acc16 = fmaf(aT[k * TS + r0 + 16], w, acc16);
        }
        float bj = b_out[j];
#pragma unroll
        for (int i = 0; i < 8; i++) {
            float a, b;
            unpack2(acc[i], a, b);
            resT[j * RS + r0 + 2 * i]     = a + bj;   // duplicated boundary rows
            resT[j * RS + r0 + 2 * i + 1] = b + bj;   // write identical bits: benign
        }
        resT[j * RS + r0 + 16] = acc16 + bj;
    }
    __syncthreads();

    // ---- phase 6: window-reverse, coalesced write ----
    float* obase = out + (size_t)batch * C * HH * WW
                       + (size_t)(wy * P) * WW + (wx * P);
    for (int i = tid; i < PP * C; i += NT) {
        int t  = i % PP;
        int ch = i / PP;
        int pi = t / P, pj = t % P;
        obase[((size_t)ch * HH + pi) * WW + pj] = resT[ch * RS + t];
    }
}

// ---------------------------------------------------------------------------
extern "C" void kernel_launch(void* const* d_in, const int* in_sizes, int n_in,
                              void* d_out, int out_size) {
    const float* x       = (const float*)d_in[0];
    const float* w_qkv   = (const float*)d_in[1];
    const float* b_qkv   = (const float*)d_in[2];
    const float* rel_pos = (const float*)d_in[3];
    const float* w_out   = (const float*)d_in[4];
    const float* b_out   = (const float*)d_in[5];
    float* out           = (float*)d_out;

    prep_kernel<<<96, 256>>>(w_qkv, w_out, rel_pos);

    cudaFuncSetAttribute(win_attn_kernel,
                         cudaFuncAttributeMaxDynamicSharedMemorySize,
                         SMEM_BYTES);
    win_attn_kernel<<<BATCH * NW, NT, SMEM_BYTES>>>(x, b_qkv, b_out, out);
}

// round 8
// speedup vs baseline: 1.7986x; 1.1985x over previous
#include <cuda_runtime.h>
#include <cstdint>

// Problem constants
#define BATCH 8
#define C     192
#define HH    224
#define WW    224
#define P     7
#define PP    49          // tokens per window
#define NH    6
#define HD    32
#define NWX   32
#define NW    1024
#define C3    576
#define NT    576
#define TS    52          // transposed tile stride (floats), %4==0 for LDS.128
#define RS    49          // result-tile stride (odd -> conflict-free scalar access)

// Prep scratch
__device__ float g_wqkvT[C * C3];        // [k][j]
__device__ float g_woutT[C * C];         // [k][j]
__device__ float g_bias[NH * PP * PP];   // [h][p][q]

// ---------------------------------------------------------------------------
__global__ void prep_kernel(const float* __restrict__ w_qkv,
                            const float* __restrict__ w_out,
                            const float* __restrict__ rel_pos) {
    int tid = blockIdx.x * blockDim.x + threadIdx.x;
    int stride = gridDim.x * blockDim.x;
    for (int i = tid; i < C3 * C; i += stride) {
        int j = i / C, k = i % C;
        g_wqkvT[k * C3 + j] = w_qkv[i];
    }
    for (int i = tid; i < C * C; i += stride) {
        int j = i / C, k = i % C;
        g_woutT[k * C + j] = w_out[i];
    }
    for (int i = tid; i < NH * PP * PP; i += stride) {
        int h = i / (PP * PP);
        int rem = i % (PP * PP);
        int p = rem / PP, q = rem % PP;
        int ri = (p / P) - (q / P) + P - 1;
        int rj = (p % P) - (q % P) + P - 1;
        g_bias[i] = rel_pos[(h * (2 * P - 1) + ri) * (2 * P - 1) + rj];
    }
}

// ---------------------------------------------------------------------------
// Packed fp32x2 helpers
// ---------------------------------------------------------------------------
__device__ __forceinline__ unsigned long long pack2(float a, float b) {
    unsigned long long r;
    asm("mov.b64 %0, {%1, %2};" : "=l"(r) : "f"(a), "f"(b));
    return r;
}
__device__ __forceinline__ void unpack2(unsigned long long v, float& a, float& b) {
    asm("mov.b64 {%0, %1}, %2;" : "=f"(a), "=f"(b) : "l"(v));
}
__device__ __forceinline__ void ffma2(unsigned long long& d,
                                      unsigned long long a,
                                      unsigned long long b) {
    asm("fma.rn.f32x2 %0, %1, %2, %0;" : "+l"(d) : "l"(a), "l"(b));
}

// ---------------------------------------------------------------------------
// smem layout (floats):
//   xsT  : 192 x 52  [ch][t]   (phases 1-2; reused as aT, attn output, 4-5)
//   qkv  : 49 x 576  [t][j]    (phases 2-4; reused as resT 192 x 49, 5-6)
//   probs: 294 x 49  [h*49+p][q]
// ---------------------------------------------------------------------------
#define SMEM_FLOATS (C * TS + PP * C3 + NH * PP * PP)
#define SMEM_BYTES  (SMEM_FLOATS * 4)

__global__ void __launch_bounds__(NT, 1)
win_attn_kernel(const float* __restrict__ x,
                const float* __restrict__ b_qkv,
                const float* __restrict__ b_out,
                float* __restrict__ out) {
    extern __shared__ float smem[];
    float* xsT   = smem;                 // [ch][t] stride TS ; later aT
    float* qkv   = smem + C * TS;        // [t][j]  stride C3 ; later resT (stride RS)
    float* probs = qkv + PP * C3;        // [tid][q] stride RS

    const int bx    = blockIdx.x;
    const int batch = bx / NW;
    const int win   = bx % NW;
    const int wy    = win / NWX;
    const int wx    = win % NWX;
    const int tid   = threadIdx.x;

    // ---- phase 1: load window, transposed into smem ----
    const float* xbase = x + (size_t)batch * C * HH * WW
                           + (size_t)(wy * P) * WW + (wx * P);
    for (int i = tid; i < PP * C; i += NT) {
        int t  = i % PP;
        int ch = i / PP;
        int pi = t / P, pj = t % P;
        xsT[ch * TS + t] = xbase[((size_t)ch * HH + pi) * WW + pj];
    }
    __syncthreads();

    // ---- phase 2: QKV GEMM. 2 output columns x half the rows per thread. ----
    // thread = (jj in 0..287, rh in 0..1). cols {jj, jj+288};
    // rh=0: rows 0..23 (12 ull), rh=1: rows 24..47 (12 ull) + row 48 scalar.
    {
        const int jj = tid % 288;
        const int rh = tid / 288;            // warp-uniform (288 = 9 warps)
        const int r0 = rh * 24;
        unsigned long long acc0[12], acc1[12];
        float e0 = 0.f, e1 = 0.f;
#pragma unroll
        for (int i = 0; i < 12; i++) { acc0[i] = 0ULL; acc1[i] = 0ULL; }
        const float* wp0 = g_wqkvT + jj;
        const float* wp1 = g_wqkvT + jj + 288;
        for (int k = 0; k < C; k++) {
            float w0 = wp0[k * C3];                  // coalesced LDG (L2-hot)
            float w1 = wp1[k * C3];
            unsigned long long ww0 = pack2(w0, w0);
            unsigned long long ww1 = pack2(w1, w1);
            const ulonglong2* xr = (const ulonglong2*)(xsT + k * TS + r0);
#pragma unroll
            for (int i = 0; i < 6; i++) {            // 6 x LDS.128 per k
                ulonglong2 v = xr[i];
                ffma2(acc0[2 * i],     v.x, ww0);
                ffma2(acc0[2 * i + 1], v.y, ww0);
                ffma2(acc1[2 * i],     v.x, ww1);
                ffma2(acc1[2 * i + 1], v.y, ww1);
            }
            if (rh) {
                float xv = xsT[k * TS + 48];
                e0 = fmaf(xv, w0, e0);
                e1 = fmaf(xv, w1, e1);
            }
        }
        float b0 = b_qkv[jj];
        float b1 = b_qkv[jj + 288];
        float* d0 = qkv + jj;
        float* d1 = qkv + jj + 288;
#pragma unroll
        for (int i = 0; i < 12; i++) {
            float a, b;
            unpack2(acc0[i], a, b);
            d0[(r0 + 2 * i) * C3]     = a + b0;
            d0[(r0 + 2 * i + 1) * C3] = b + b0;
            unpack2(acc1[i], a, b);
            d1[(r0 + 2 * i) * C3]     = a + b1;
            d1[(r0 + 2 * i + 1) * C3] = b + b1;
        }
        if (rh) {
            d0[48 * C3] = e0 + b0;
            d1[48 * C3] = e1 + b1;
        }
    }
    __syncthreads();

    // ---- phase 3+4: attention. thread = (head, row). packed dot products ----
    float* aT = xsT;  // reuse (xsT dead after phase 2)
    if (tid < NH * PP) {
        const int h = tid / PP, p = tid % PP;
        const float scale = 0.1767766952966369f;  // 1/sqrt(32)

        unsigned long long qv[16];
        {
            const ulonglong2* qp = (const ulonglong2*)(qkv + p * C3 + h * HD);
#pragma unroll
            for (int i = 0; i < 8; i++) {
                ulonglong2 v = qp[i];
                qv[2 * i] = v.x; qv[2 * i + 1] = v.y;
            }
        }

        float* prow = probs + tid * RS;
        const float* brow = g_bias + (h * PP + p) * PP;

        float mx = -1e30f;
        for (int q = 0; q < PP; q++) {
            const ulonglong2* kp = (const ulonglong2*)(qkv + q * C3 + C + h * HD);
            unsigned long long a0 = 0ULL, a1 = 0ULL;
#pragma unroll
            for (int i = 0; i < 8; i++) {
                ulonglong2 v = kp[i];
                ffma2(a0, qv[2 * i],     v.x);
                ffma2(a1, qv[2 * i + 1], v.y);
            }
            float s0, s1, s2, s3;
            unpack2(a0, s0, s1);
            unpack2(a1, s2, s3);
            float s = ((s0 + s1) + (s2 + s3)) * scale + brow[q];
            prow[q] = s;
            mx = fmaxf(mx, s);
        }
        float sum = 0.f;
        for (int q = 0; q < PP; q++) {
            float e = __expf(prow[q] - mx);
            prow[q] = e;
            sum += e;
        }
        float inv = 1.f / sum;

        unsigned long long acc[16];
#pragma unroll
        for (int i = 0; i < 16; i++) acc[i] = 0ULL;
        for (int q = 0; q < PP; q++) {
            float pr = prow[q] * inv;
            unsigned long long pp2 = pack2(pr, pr);
            const ulonglong2* vp = (const ulonglong2*)(qkv + q * C3 + 2 * C + h * HD);
#pragma unroll
            for (int i = 0; i < 8; i++) {
                ulonglong2 v = vp[i];
                ffma2(acc[2 * i],     v.x, pp2);
                ffma2(acc[2 * i + 1], v.y, pp2);
            }
        }
        // store transposed: aT[(h*32+d)][p]
#pragma unroll
        for (int i = 0; i < 16; i++) {
            float a, b;
            unpack2(acc[i], a, b);
            aT[(h * HD + 2 * i) * TS + p]     = a;
            aT[(h * HD + 2 * i + 1) * TS + p] = b;
        }
    }
    __syncthreads();

    // ---- phase 5: output projection. 2 cols x 8-row groups per thread ----
    // thread = (j in 0..95, rg in 0..5). cols {j, j+96};
    // rows 8*rg .. 8*rg+7, plus row 48 handled by rg==5.
    float* resT = qkv;  // reuse, layout [ch][t] stride RS
    {
        const int j  = tid % 96;
        const int rg = tid / 96;             // warp-uniform (96 = 3 warps)
        const int r0 = rg * 8;
        unsigned long long acc0[4], acc1[4];
        float e0 = 0.f, e1 = 0.f;
#pragma unroll
        for (int i = 0; i < 4; i++) { acc0[i] = 0ULL; acc1[i] = 0ULL; }
        const float* wp0 = g_woutT + j;
        const float* wp1 = g_woutT + j + 96;
        const bool last = (rg == 5);
        for (int k = 0; k < C; k++) {
            float w0 = wp0[k * C];
            float w1 = wp1[k * C];
            unsigned long long ww0 = pack2(w0, w0);
            unsigned long long ww1 = pack2(w1, w1);
            const ulonglong2* xr = (const ulonglong2*)(aT + k * TS + r0);
#pragma unroll
            for (int i = 0; i < 2; i++) {            // 2 x LDS.128 per k
                ulonglong2 v = xr[i];
                ffma2(acc0[2 * i],     v.x, ww0);
                ffma2(acc0[2 * i + 1], v.y, ww0);
                ffma2(acc1[2 * i],     v.x, ww1);
                ffma2(acc1[2 * i + 1], v.y, ww1);
            }
            if (last) {
                float xv = aT[k * TS + 48];
                e0 = fmaf(xv, w0, e0);
                e1 = fmaf(xv, w1, e1);
            }
        }
        float b0 = b_out[j];
        float b1 = b_out[j + 96];
#pragma unroll
        for (int i = 0; i < 4; i++) {
            float a, b;
            unpack2(acc0[i], a, b);
            resT[j * RS + r0 + 2 * i]     = a + b0;
            resT[j * RS + r0 + 2 * i + 1] = b + b0;
            unpack2(acc1[i], a, b);
            resT[(j + 96) * RS + r0 + 2 * i]     = a + b1;
            resT[(j + 96) * RS + r0 + 2 * i + 1] = b + b1;
        }
        if (last) {
            resT[j * RS + 48]        = e0 + b0;
            resT[(j + 96) * RS + 48] = e1 + b1;
        }
    }
    __syncthreads();

    // ---- phase 6: window-reverse, coalesced write ----
    float* obase = out + (size_t)batch * C * HH * WW
                       + (size_t)(wy * P) * WW + (wx * P);
    for (int i = tid; i < PP * C; i += NT) {
        int t  = i % PP;
        int ch = i / PP;
        int pi = t / P, pj = t % P;
        obase[((size_t)ch * HH + pi) * WW + pj] = resT[ch * RS + t];
    }
}

// ---------------------------------------------------------------------------
extern "C" void kernel_launch(void* const* d_in, const int* in_sizes, int n_in,
                              void* d_out, int out_size) {
    const float* x       = (const float*)d_in[0];
    const float* w_qkv   = (const float*)d_in[1];
    const float* b_qkv   = (const float*)d_in[2];
    const float* rel_pos = (const float*)d_in[3];
    const float* w_out   = (const float*)d_in[4];
    const float* b_out   = (const float*)d_in[5];
    float* out           = (float*)d_out;

    prep_kernel<<<96, 256>>>(w_qkv, w_out, rel_pos);

    cudaFuncSetAttribute(win_attn_kernel,
                         cudaFuncAttributeMaxDynamicSharedMemorySize,
                         SMEM_BYTES);
    win_attn_kernel<<<BATCH * NW, NT, SMEM_BYTES>>>(x, b_qkv, b_out, out);
}

// round 9
// speedup vs baseline: 2.4970x; 1.3883x over previous
#include <cuda_runtime.h>
#include <cuda_bf16.h>
#include <cstdint>

// Problem constants
#define BATCH 8
#define C     192
#define HH    224
#define WW    224
#define P     7
#define PP    49          // tokens per window
#define NH    6
#define HD    32
#define NWX   32
#define NW    1024
#define C3    576
#define NT    576
#define TS    52          // aT stride (floats)
#define RS    49          // result-tile stride
#define KS    12          // k-steps of 16 (K=192)
#define NTL   72          // n-tiles of 8  (N=576)

// Prep scratch
__device__ uint4 g_bfrag[KS * NTL * 32];   // [ks][nt][lane] = {b0_hi,b1_hi,b0_lo,b1_lo}
__device__ float g_woutT[C * C];           // [k][j]
__device__ float g_bias[NH * PP * PP];     // [h][p][q]

// ---------------------------------------------------------------------------
__device__ __forceinline__ uint32_t pk_bf16x2(float a, float b) {
    __nv_bfloat16 ba = __float2bfloat16(a);
    __nv_bfloat16 bb = __float2bfloat16(b);
    return ((uint32_t)__bfloat16_as_ushort(bb) << 16) | __bfloat16_as_ushort(ba);
}

__global__ void prep_kernel(const float* __restrict__ w_qkv,
                            const float* __restrict__ w_out,
                            const float* __restrict__ rel_pos) {
    int tid = blockIdx.x * blockDim.x + threadIdx.x;
    int stride = gridDim.x * blockDim.x;
    // B fragments for QKV mma: B[k][n] = w_qkv[n*C + k]
    for (int i = tid; i < KS * NTL * 32; i += stride) {
        int ks   = i / (NTL * 32);
        int rem  = i % (NTL * 32);
        int nt   = rem / 32;
        int lane = rem % 32;
        int g = lane >> 2, tig = lane & 3;
        int n  = nt * 8 + g;
        int k0 = ks * 16 + 2 * tig;
        float v00 = w_qkv[n * C + k0];
        float v01 = w_qkv[n * C + k0 + 1];
        float v10 = w_qkv[n * C + k0 + 8];
        float v11 = w_qkv[n * C + k0 + 9];
        float h00 = __bfloat162float(__float2bfloat16(v00));
        float h01 = __bfloat162float(__float2bfloat16(v01));
        float h10 = __bfloat162float(__float2bfloat16(v10));
        float h11 = __bfloat162float(__float2bfloat16(v11));
        uint4 r;
        r.x = pk_bf16x2(h00, h01);
        r.y = pk_bf16x2(h10, h11);
        r.z = pk_bf16x2(v00 - h00, v01 - h01);
        r.w = pk_bf16x2(v10 - h10, v11 - h11);
        g_bfrag[i] = r;
    }
    for (int i = tid; i < C * C; i += stride) {
        int j = i / C, k = i % C;
        g_woutT[k * C + j] = w_out[i];
    }
    for (int i = tid; i < NH * PP * PP; i += stride) {
        int h = i / (PP * PP);
        int rem = i % (PP * PP);
        int p = rem / PP, q = rem % PP;
        int ri = (p / P) - (q / P) + P - 1;
        int rj = (p % P) - (q % P) + P - 1;
        g_bias[i] = rel_pos[(h * (2 * P - 1) + ri) * (2 * P - 1) + rj];
    }
}

// ---------------------------------------------------------------------------
// Packed fp32x2 helpers (attention + out-proj)
// ---------------------------------------------------------------------------
__device__ __forceinline__ unsigned long long pack2(float a, float b) {
    unsigned long long r;
    asm("mov.b64 %0, {%1, %2};" : "=l"(r) : "f"(a), "f"(b));
    return r;
}
__device__ __forceinline__ void unpack2(unsigned long long v, float& a, float& b) {
    asm("mov.b64 {%0, %1}, %2;" : "=f"(a), "=f"(b) : "l"(v));
}
__device__ __forceinline__ void ffma2(unsigned long long& d,
                                      unsigned long long a,
                                      unsigned long long b) {
    asm("fma.rn.f32x2 %0, %1, %2, %0;" : "+l"(d) : "l"(a), "l"(b));
}

// bf16 mma m16n8k16, fp32 accumulate
__device__ __forceinline__ void mma16816(float c[4], uint4 a,
                                         uint32_t b0, uint32_t b1) {
    asm("mma.sync.aligned.m16n8k16.row.col.f32.bf16.bf16.f32 "
        "{%0,%1,%2,%3}, {%4,%5,%6,%7}, {%8,%9}, {%0,%1,%2,%3};"
        : "+f"(c[0]), "+f"(c[1]), "+f"(c[2]), "+f"(c[3])
        : "r"(a.x), "r"(a.y), "r"(a.z), "r"(a.w), "r"(b0), "r"(b1));
}

// ---------------------------------------------------------------------------
// smem layout (floats):
//   region0: 12288 floats (49152 B)
//            phase 1-2: x fragments [mt][ks][lane]{hi 16B, lo 16B} (swizzled)
//            phase 4-5: aT, attention output [ch][t] stride TS (39.9 KB)
//   qkv   : 49 x 576  [t][j]        (phases 2-4; reused as resT [ch][t] RS)
//   probs : 294 x 49
// ---------------------------------------------------------------------------
#define FRAG_FLOATS 12288
#define SMEM_FLOATS (FRAG_FLOATS + PP * C3 + NH * PP * PP)
#define SMEM_BYTES  (SMEM_FLOATS * 4)

__global__ void __launch_bounds__(NT, 1)
win_attn_kernel(const float* __restrict__ x,
                const float* __restrict__ b_qkv,
                const float* __restrict__ b_out,
                float* __restrict__ out) {
    extern __shared__ float smem[];
    float* aT    = smem;                     // phase 4-5 (overlaps fragments)
    float* qkv   = smem + FRAG_FLOATS;       // [t][j] stride C3 ; later resT
    float* probs = qkv + PP * C3;

    const int bx    = blockIdx.x;
    const int batch = bx / NW;
    const int win   = bx % NW;
    const int wy    = win / NWX;
    const int wx    = win % NWX;
    const int tid   = threadIdx.x;

    // ---- phase 1: load window -> bf16 hi/lo fragments in smem ----
    const float* xbase = x + (size_t)batch * C * HH * WW
                           + (size_t)(wy * P) * WW + (wx * P);
    for (int i = tid; i < 64 * C; i += NT) {
        int t  = i & 63;
        int ch = i >> 6;
        float v = 0.f;
        if (t < PP) v = xbase[((size_t)ch * HH + (t / 7)) * WW + (t % 7)];
        __nv_bfloat16 hi = __float2bfloat16(v);
        __nv_bfloat16 lo = __float2bfloat16(v - __bfloat162float(hi));
        int mt = t >> 4, r = t & 15;
        int ks = ch >> 4, c = ch & 15;
        int reg  = ((r >> 3) & 1) + ((c >> 3) << 1);
        int lane = (r & 7) * 4 + ((c & 7) >> 1);
        int half = c & 1;
        int sw   = (lane & 4) ? 16 : 0;
        char* base = (char*)smem + ((mt * KS + ks) * 32 + lane) * 32;
        ((__nv_bfloat16*)(base + sw))[reg * 2 + half]        = hi;
        ((__nv_bfloat16*)(base + (16 - sw)))[reg * 2 + half] = lo;
    }
    __syncthreads();

    // ---- phase 2: QKV GEMM on tensor cores (bf16-split, 3 mma/tile) ----
    {
        const int w    = tid >> 5;      // 0..17 = n-group
        const int lane = tid & 31;
        const int g    = lane >> 2, tig = lane & 3;
        const int ng   = w;
        const int sw   = (lane & 4) ? 16 : 0;

        for (int mtp = 0; mtp < 2; mtp++) {
            float acc[2][4][4];
#pragma unroll
            for (int a = 0; a < 2; a++)
#pragma unroll
                for (int b = 0; b < 4; b++)
#pragma unroll
                    for (int cc = 0; cc < 4; cc++) acc[a][b][cc] = 0.f;

            for (int ks = 0; ks < KS; ks++) {
                const char* baA = (const char*)smem
                                + (((2 * mtp) * KS + ks) * 32 + lane) * 32;
                const char* baB = baA + KS * 32 * 32;   // mt+1
                uint4 ahA = *(const uint4*)(baA + sw);
                uint4 alA = *(const uint4*)(baA + (16 - sw));
                uint4 ahB = *(const uint4*)(baB + sw);
                uint4 alB = *(const uint4*)(baB + (16 - sw));
                const uint4* bp = g_bfrag + (ks * NTL + ng * 4) * 32 + lane;
#pragma unroll
                for (int nt = 0; nt < 4; nt++) {
                    uint4 b = bp[nt * 32];
                    mma16816(acc[0][nt], ahA, b.x, b.y);   // hi*hi
                    mma16816(acc[0][nt], ahA, b.z, b.w);   // hi*lo
                    mma16816(acc[0][nt], alA, b.x, b.y);   // lo*hi
                    mma16816(acc[1][nt], ahB, b.x, b.y);
                    mma16816(acc[1][nt], ahB, b.z, b.w);
                    mma16816(acc[1][nt], alB, b.x, b.y);
                }
            }
            // epilogue: bias + store into qkv[t][j]
#pragma unroll
            for (int nt = 0; nt < 4; nt++) {
                int n = (ng * 4 + nt) * 8 + 2 * tig;
                float b0 = b_qkv[n], b1 = b_qkv[n + 1];
                int r0 = mtp * 32 + g;          // always < 49
                int r1 = r0 + 8;
                int r2 = mtp * 32 + 16 + g;
                int r3 = r2 + 8;
                *(float2*)(qkv + r0 * C3 + n) =
                    make_float2(acc[0][nt][0] + b0, acc[0][nt][1] + b1);
                if (r1 < PP)
                    *(float2*)(qkv + r1 * C3 + n) =
                        make_float2(acc[0][nt][2] + b0, acc[0][nt][3] + b1);
                if (r2 < PP)
                    *(float2*)(qkv + r2 * C3 + n) =
                        make_float2(acc[1][nt][0] + b0, acc[1][nt][1] + b1);
                if (r3 < PP)
                    *(float2*)(qkv + r3 * C3 + n) =
                        make_float2(acc[1][nt][2] + b0, acc[1][nt][3] + b1);
            }
        }
    }
    __syncthreads();

    // ---- phase 3+4: attention. thread = (head, row). ffma2 dot products ----
    if (tid < NH * PP) {
        const int h = tid / PP, p = tid % PP;
        const float scale = 0.1767766952966369f;  // 1/sqrt(32)

        unsigned long long qv[16];
        {
            const ulonglong2* qp = (const ulonglong2*)(qkv + p * C3 + h * HD);
#pragma unroll
            for (int i = 0; i < 8; i++) {
                ulonglong2 v = qp[i];
                qv[2 * i] = v.x; qv[2 * i + 1] = v.y;
            }
        }

        float* prow = probs + tid * RS;
        const float* brow = g_bias + (h * PP + p) * PP;

        float mx = -1e30f;
        for (int q = 0; q < PP; q++) {
            const ulonglong2* kp = (const ulonglong2*)(qkv + q * C3 + C + h * HD);
            unsigned long long a0 = 0ULL, a1 = 0ULL;
#pragma unroll
            for (int i = 0; i < 8; i++) {
                ulonglong2 v = kp[i];
                ffma2(a0, qv[2 * i],     v.x);
                ffma2(a1, qv[2 * i + 1], v.y);
            }
            float s0, s1, s2, s3;
            unpack2(a0, s0, s1);
            unpack2(a1, s2, s3);
            float s = ((s0 + s1) + (s2 + s3)) * scale + brow[q];
            prow[q] = s;
            mx = fmaxf(mx, s);
        }
        float sum = 0.f;
        for (int q = 0; q < PP; q++) {
            float e = __expf(prow[q] - mx);
            prow[q] = e;
            sum += e;
        }
        float inv = 1.f / sum;

        unsigned long long acc[16];
#pragma unroll
        for (int i = 0; i < 16; i++) acc[i] = 0ULL;
        for (int q = 0; q < PP; q++) {
            float pr = prow[q] * inv;
            unsigned long long pp2 = pack2(pr, pr);
            const ulonglong2* vp = (const ulonglong2*)(qkv + q * C3 + 2 * C + h * HD);
#pragma unroll
            for (int i = 0; i < 8; i++) {
                ulonglong2 v = vp[i];
                ffma2(acc[2 * i],     v.x, pp2);
                ffma2(acc[2 * i + 1], v.y, pp2);
            }
        }
        // store transposed: aT[(h*32+d)][p]  (fragments dead now)
#pragma unroll
        for (int i = 0; i < 16; i++) {
            float a, b;
            unpack2(acc[i], a, b);
            aT[(h * HD + 2 * i) * TS + p]     = a;
            aT[(h * HD + 2 * i + 1) * TS + p] = b;
        }
    }
    __syncthreads();

    // ---- phase 5: output projection. 2 cols x 8-row groups per thread ----
    float* resT = qkv;  // reuse, layout [ch][t] stride RS
    {
        const int j  = tid % 96;
        const int rg = tid / 96;             // warp-uniform
        const int r0 = rg * 8;
        unsigned long long acc0[4], acc1[4];
        float e0 = 0.f, e1 = 0.f;
#pragma unroll
        for (int i = 0; i < 4; i++) { acc0[i] = 0ULL; acc1[i] = 0ULL; }
        const float* wp0 = g_woutT + j;
        const float* wp1 = g_woutT + j + 96;
        const bool last = (rg == 5);
        for (int k = 0; k < C; k++) {
            float w0 = wp0[k * C];
            float w1 = wp1[k * C];
            unsigned long long ww0 = pack2(w0, w0);
            unsigned long long ww1 = pack2(w1, w1);
            const ulonglong2* xr = (const ulonglong2*)(aT + k * TS + r0);
#pragma unroll
            for (int i = 0; i < 2; i++) {
                ulonglong2 v = xr[i];
                ffma2(acc0[2 * i],     v.x, ww0);
                ffma2(acc0[2 * i + 1], v.y, ww0);
                ffma2(acc1[2 * i],     v.x, ww1);
                ffma2(acc1[2 * i + 1], v.y, ww1);
            }
            if (last) {
                float xv = aT[k * TS + 48];
                e0 = fmaf(xv, w0, e0);
                e1 = fmaf(xv, w1, e1);
            }
        }
        float b0 = b_out[j];
        float b1 = b_out[j + 96];
#pragma unroll
        for (int i = 0; i < 4; i++) {
            float a, b;
            unpack2(acc0[i], a, b);
            resT[j * RS + r0 + 2 * i]     = a + b0;
            resT[j * RS + r0 + 2 * i + 1] = b + b0;
            unpack2(acc1[i], a, b);
            resT[(j + 96) * RS + r0 + 2 * i]     = a + b1;
            resT[(j + 96) * RS + r0 + 2 * i + 1] = b + b1;
        }
        if (last) {
            resT[j * RS + 48]        = e0 + b0;
            resT[(j + 96) * RS + 48] = e1 + b1;
        }
    }
    __syncthreads();

    // ---- phase 6: window-reverse, coalesced write ----
    float* obase = out + (size_t)batch * C * HH * WW
                       + (size_t)(wy * P) * WW + (wx * P);
    for (int i = tid; i < PP * C; i += NT) {
        int t  = i % PP;
        int ch = i / PP;
        int pi = t / P, pj = t % P;
        obase[((size_t)ch * HH + pi) * WW + pj] = resT[ch * RS + t];
    }
}

// ---------------------------------------------------------------------------
extern "C" void kernel_launch(void* const* d_in, const int* in_sizes, int n_in,
                              void* d_out, int out_size) {
    const float* x       = (const float*)d_in[0];
    const float* w_qkv   = (const float*)d_in[1];
    const float* b_qkv   = (const float*)d_in[2];
    const float* rel_pos = (const float*)d_in[3];
    const float* w_out   = (const float*)d_in[4];
    const float* b_out   = (const float*)d_in[5];
    float* out           = (float*)d_out;

    prep_kernel<<<96, 256>>>(w_qkv, w_out, rel_pos);

    cudaFuncSetAttribute(win_attn_kernel,
                         cudaFuncAttributeMaxDynamicSharedMemorySize,
                         SMEM_BYTES);
    win_attn_kernel<<<BATCH * NW, NT, SMEM_BYTES>>>(x, b_qkv, b_out, out);
}

// round 11
// speedup vs baseline: 2.8448x; 1.1393x over previous
#include <cuda_runtime.h>
#include <cuda_bf16.h>
#include <cstdint>

// Problem constants
#define BATCH 8
#define C     192
#define HH    224
#define WW    224
#define P     7
#define PP    49          // tokens per window
#define NH    6
#define HD    32
#define NWX   32
#define NW    1024
#define C3    576
#define NT    576
#define RS    49          // result-tile stride (floats)
#define QS    584         // fp32 qkv buffer stride (bank-spread; %4==0)
#define KS    12          // k-steps of 16 (K=192)
#define NTL   72          // qkv n-tiles of 8 (N=576)
#define NTO   24          // out-proj n-tiles of 8 (N=192)

// Prep scratch
__device__ uint4 g_bfrag[KS * NTL * 32];   // qkv  B frags {b0h,b1h,b0l,b1l}
__device__ uint4 g_bofrag[KS * NTO * 32];  // wout B frags
__device__ float g_bias[NH * PP * PP];     // [h][p][q]

// ---------------------------------------------------------------------------
__device__ __forceinline__ uint32_t pk_bf16x2(float a, float b) {
    __nv_bfloat16 ba = __float2bfloat16(a);
    __nv_bfloat16 bb = __float2bfloat16(b);
    return ((uint32_t)__bfloat16_as_ushort(bb) << 16) | __bfloat16_as_ushort(ba);
}

__global__ void prep_kernel(const float* __restrict__ w_qkv,
                            const float* __restrict__ w_out,
                            const float* __restrict__ rel_pos) {
    int tid = blockIdx.x * blockDim.x + threadIdx.x;
    int stride = gridDim.x * blockDim.x;
    // B fragments for QKV mma: B[k][n] = w_qkv[n*C + k]
    for (int i = tid; i < KS * NTL * 32; i += stride) {
        int ks   = i / (NTL * 32);
        int rem  = i % (NTL * 32);
        int nt   = rem / 32;
        int lane = rem % 32;
        int g = lane >> 2, tig = lane & 3;
        int n  = nt * 8 + g;
        int k0 = ks * 16 + 2 * tig;
        float v00 = w_qkv[n * C + k0];
        float v01 = w_qkv[n * C + k0 + 1];
        float v10 = w_qkv[n * C + k0 + 8];
        float v11 = w_qkv[n * C + k0 + 9];
        float h00 = __bfloat162float(__float2bfloat16(v00));
        float h01 = __bfloat162float(__float2bfloat16(v01));
        float h10 = __bfloat162float(__float2bfloat16(v10));
        float h11 = __bfloat162float(__float2bfloat16(v11));
        uint4 r;
        r.x = pk_bf16x2(h00, h01);
        r.y = pk_bf16x2(h10, h11);
        r.z = pk_bf16x2(v00 - h00, v01 - h01);
        r.w = pk_bf16x2(v10 - h10, v11 - h11);
        g_bfrag[i] = r;
    }
    // B fragments for out-proj mma: B[k][n] = w_out[n*C + k]
    for (int i = tid; i < KS * NTO * 32; i += stride) {
        int ks   = i / (NTO * 32);
        int rem  = i % (NTO * 32);
        int nt   = rem / 32;
        int lane = rem % 32;
        int g = lane >> 2, tig = lane & 3;
        int n  = nt * 8 + g;
        int k0 = ks * 16 + 2 * tig;
        float v00 = w_out[n * C + k0];
        float v01 = w_out[n * C + k0 + 1];
        float v10 = w_out[n * C + k0 + 8];
        float v11 = w_out[n * C + k0 + 9];
        float h00 = __bfloat162float(__float2bfloat16(v00));
        float h01 = __bfloat162float(__float2bfloat16(v01));
        float h10 = __bfloat162float(__float2bfloat16(v10));
        float h11 = __bfloat162float(__float2bfloat16(v11));
        uint4 r;
        r.x = pk_bf16x2(h00, h01);
        r.y = pk_bf16x2(h10, h11);
        r.z = pk_bf16x2(v00 - h00, v01 - h01);
        r.w = pk_bf16x2(v10 - h10, v11 - h11);
        g_bofrag[i] = r;
    }
    for (int i = tid; i < NH * PP * PP; i += stride) {
        int h = i / (PP * PP);
        int rem = i % (PP * PP);
        int p = rem / PP, q = rem % PP;
        int ri = (p / P) - (q / P) + P - 1;
        int rj = (p % P) - (q % P) + P - 1;
        g_bias[i] = rel_pos[(h * (2 * P - 1) + ri) * (2 * P - 1) + rj];
    }
}

// ---------------------------------------------------------------------------
// Packed fp32x2 helpers (attention)
// ---------------------------------------------------------------------------
__device__ __forceinline__ unsigned long long pack2(float a, float b) {
    unsigned long long r;
    asm("mov.b64 %0, {%1, %2};" : "=l"(r) : "f"(a), "f"(b));
    return r;
}
__device__ __forceinline__ void unpack2(unsigned long long v, float& a, float& b) {
    asm("mov.b64 {%0, %1}, %2;" : "=f"(a), "=f"(b) : "l"(v));
}
__device__ __forceinline__ void ffma2(unsigned long long& d,
                                      unsigned long long a,
                                      unsigned long long b) {
    asm("fma.rn.f32x2 %0, %1, %2, %0;" : "+l"(d) : "l"(a), "l"(b));
}

// bf16 mma m16n8k16, fp32 accumulate
__device__ __forceinline__ void mma16816(float c[4], uint4 a,
                                         uint32_t b0, uint32_t b1) {
    asm("mma.sync.aligned.m16n8k16.row.col.f32.bf16.bf16.f32 "
        "{%0,%1,%2,%3}, {%4,%5,%6,%7}, {%8,%9}, {%0,%1,%2,%3};"
        : "+f"(c[0]), "+f"(c[1]), "+f"(c[2]), "+f"(c[3])
        : "r"(a.x), "r"(a.y), "r"(a.z), "r"(a.w), "r"(b0), "r"(b1));
}

// ---------------------------------------------------------------------------
// smem layout (floats):
//   frag : 12288 floats (48 KB). phase 1-2: x A-fragments (hi/lo bf16,
//          32B/lane cell, hi/lo swizzled). phase 4-5: attn-out A-fragments.
//   qkv  : 49 x QS(584) fp32 [t][j]  (phases 2-4; reused as resT [ch][t] RS)
//   probs: 294 x 49
// ---------------------------------------------------------------------------
#define FRAG_FLOATS 12288
#define SMEM_FLOATS (FRAG_FLOATS + PP * QS + NH * PP * PP)
#define SMEM_BYTES  (SMEM_FLOATS * 4)

__global__ void __launch_bounds__(NT, 1)
win_attn_kernel(const float* __restrict__ x,
                const float* __restrict__ b_qkv,
                const float* __restrict__ b_out,
                float* __restrict__ out) {
    extern __shared__ float smem[];
    float* qkv   = smem + FRAG_FLOATS;       // [t][j] stride QS ; later resT
    float* probs = qkv + PP * QS;

    const int bx    = blockIdx.x;
    const int batch = bx / NW;
    const int win   = bx % NW;
    const int wy    = win / NWX;
    const int wx    = win % NWX;
    const int tid   = threadIdx.x;

    // ---- phase 1: load window -> bf16 hi/lo A-fragments (pair words) ----
    const float* xbase = x + (size_t)batch * C * HH * WW
                           + (size_t)(wy * P) * WW + (wx * P);
    for (int i = tid; i < 96 * 64; i += NT) {
        int t  = i & 63;
        int cp = i >> 6;                 // channel pair 0..95
        int ch = cp * 2;
        float v0 = 0.f, v1 = 0.f;
        if (t < PP) {
            const float* px = xbase + ((size_t)(t / 7)) * WW + (t % 7);
            v0 = px[(size_t)ch * HH * WW];
            v1 = px[(size_t)(ch + 1) * HH * WW];
        }
        float h0 = __bfloat162float(__float2bfloat16(v0));
        float h1 = __bfloat162float(__float2bfloat16(v1));
        uint32_t hw = pk_bf16x2(h0, h1);
        uint32_t lw = pk_bf16x2(v0 - h0, v1 - h1);
        int mt = t >> 4, r = t & 15;
        int ks = ch >> 4, c = ch & 15;   // c even
        int reg  = ((r >> 3) & 1) + ((c >> 3) << 1);
        int lane = (r & 7) * 4 + ((c & 7) >> 1);
        int sw   = (lane & 4) ? 16 : 0;
        char* base = (char*)smem + ((mt * KS + ks) * 32 + lane) * 32;
        *(uint32_t*)(base + sw + reg * 4)        = hw;
        *(uint32_t*)(base + (16 - sw) + reg * 4) = lw;
    }
    __syncthreads();

    // ---- phase 2: QKV GEMM on tensor cores (bf16-split, 3 mma/tile) ----
    {
        const int w    = tid >> 5;      // 0..17 = n-group
        const int lane = tid & 31;
        const int g    = lane >> 2, tig = lane & 3;
        const int sw   = (lane & 4) ? 16 : 0;

        for (int mtp = 0; mtp < 2; mtp++) {
            float acc[2][4][4];
#pragma unroll
            for (int a = 0; a < 2; a++)
#pragma unroll
                for (int b = 0; b < 4; b++)
#pragma unroll
                    for (int cc = 0; cc < 4; cc++) acc[a][b][cc] = 0.f;

            for (int ks = 0; ks < KS; ks++) {
                const char* baA = (const char*)smem
                                + (((2 * mtp) * KS + ks) * 32 + lane) * 32;
                const char* baB = baA + KS * 32 * 32;   // mt+1
                uint4 ahA = *(const uint4*)(baA + sw);
                uint4 alA = *(const uint4*)(baA + (16 - sw));
                uint4 ahB = *(const uint4*)(baB + sw);
                uint4 alB = *(const uint4*)(baB + (16 - sw));
                const uint4* bp = g_bfrag + (ks * NTL + w * 4) * 32 + lane;
#pragma unroll
                for (int nt = 0; nt < 4; nt++) {
                    uint4 b = bp[nt * 32];
                    mma16816(acc[0][nt], ahA, b.x, b.y);   // hi*hi
                    mma16816(acc[0][nt], ahA, b.z, b.w);   // hi*lo
                    mma16816(acc[0][nt], alA, b.x, b.y);   // lo*hi
                    mma16816(acc[1][nt], ahB, b.x, b.y);
                    mma16816(acc[1][nt], ahB, b.z, b.w);
                    mma16816(acc[1][nt], alB, b.x, b.y);
                }
            }
            // epilogue: bias + store into qkv[t][j] (stride QS, bank-spread)
#pragma unroll
            for (int nt = 0; nt < 4; nt++) {
                int n = (w * 4 + nt) * 8 + 2 * tig;
                float b0 = b_qkv[n], b1 = b_qkv[n + 1];
                int r0 = mtp * 32 + g;          // always < 49
                int r1 = r0 + 8;
                int r2 = mtp * 32 + 16 + g;
                int r3 = r2 + 8;
                *(float2*)(qkv + r0 * QS + n) =
                    make_float2(acc[0][nt][0] + b0, acc[0][nt][1] + b1);
                if (r1 < PP)
                    *(float2*)(qkv + r1 * QS + n) =
                        make_float2(acc[0][nt][2] + b0, acc[0][nt][3] + b1);
                if (r2 < PP)
                    *(float2*)(qkv + r2 * QS + n) =
                        make_float2(acc[1][nt][0] + b0, acc[1][nt][1] + b1);
                if (r3 < PP)
                    *(float2*)(qkv + r3 * QS + n) =
                        make_float2(acc[1][nt][2] + b0, acc[1][nt][3] + b1);
            }
        }
    }
    __syncthreads();

    // ---- phase 3+4: attention. thread = (head, row). ffma2 dot products.
    //      epilogue writes attn-out directly as bf16 hi/lo A-fragments.  ----
    if (tid < NH * PP) {
        const int h = tid / PP, p = tid % PP;
        const float scale = 0.1767766952966369f;  // 1/sqrt(32)

        unsigned long long qv[16];
        {
            const ulonglong2* qp = (const ulonglong2*)(qkv + p * QS + h * HD);
#pragma unroll
            for (int i = 0; i < 8; i++) {
                ulonglong2 v = qp[i];
                qv[2 * i] = v.x; qv[2 * i + 1] = v.y;
            }
        }

        float* prow = probs + tid * RS;
        const float* brow = g_bias + (h * PP + p) * PP;

        float mx = -1e30f;
        for (int q = 0; q < PP; q++) {
            const ulonglong2* kp = (const ulonglong2*)(qkv + q * QS + C + h * HD);
            unsigned long long a0 = 0ULL, a1 = 0ULL;
#pragma unroll
            for (int i = 0; i < 8; i++) {
                ulonglong2 v = kp[i];
                ffma2(a0, qv[2 * i],     v.x);
                ffma2(a1, qv[2 * i + 1], v.y);
            }
            float s0, s1, s2, s3;
            unpack2(a0, s0, s1);
            unpack2(a1, s2, s3);
            float s = ((s0 + s1) + (s2 + s3)) * scale + brow[q];
            prow[q] = s;
            mx = fmaxf(mx, s);
        }
        float sum = 0.f;
        for (int q = 0; q < PP; q++) {
            float e = __expf(prow[q] - mx);
            prow[q] = e;
            sum += e;
        }
        float inv = 1.f / sum;

        unsigned long long acc[16];
#pragma unroll
        for (int i = 0; i < 16; i++) acc[i] = 0ULL;
        for (int q = 0; q < PP; q++) {
            float pr = prow[q] * inv;
            unsigned long long pp2 = pack2(pr, pr);
            const ulonglong2* vp = (const ulonglong2*)(qkv + q * QS + 2 * C + h * HD);
#pragma unroll
            for (int i = 0; i < 8; i++) {
                ulonglong2 v = vp[i];
                ffma2(acc[2 * i],     v.x, pp2);
                ffma2(acc[2 * i + 1], v.y, pp2);
            }
        }
        // epilogue: write bf16 hi/lo A-fragments for the out-proj GEMM
        {
            int mt = p >> 4, r = p & 15;
            int lane_r = (r & 7) * 4;
            int reg_r  = (r >> 3) & 1;
#pragma unroll
            for (int i = 0; i < 16; i++) {
                float a, b;
                unpack2(acc[i], a, b);
                int ch = h * HD + 2 * i;
                int ks = ch >> 4, c = ch & 15;
                float ha = __bfloat162float(__float2bfloat16(a));
                float hb = __bfloat162float(__float2bfloat16(b));
                uint32_t hw = pk_bf16x2(ha, hb);
                uint32_t lw = pk_bf16x2(a - ha, b - hb);
                int reg  = reg_r + ((c >> 3) << 1);
                int lane = lane_r + ((c & 7) >> 1);
                int sw   = (lane & 4) ? 16 : 0;
                char* base = (char*)smem + ((mt * KS + ks) * 32 + lane) * 32;
                *(uint32_t*)(base + sw + reg * 4)        = hw;
                *(uint32_t*)(base + (16 - sw) + reg * 4) = lw;
            }
        }
    }
    __syncthreads();

    // ---- phase 5: output projection on tensor cores (bf16-split) ----
    // 16 warps: mt = w>>2 (4 m-tiles), ngrp = w&3 (6 n-tiles = 48 cols each).
    float* resT = qkv;  // reuse, layout [ch][t] stride RS
    {
        const int w    = tid >> 5;
        const int lane = tid & 31;
        const int g    = lane >> 2, tig = lane & 3;
        const int sw   = (lane & 4) ? 16 : 0;
        if (w < 16) {
            const int mt   = w >> 2;
            const int ngrp = w & 3;
            float acc[6][4];
#pragma unroll
            for (int nt = 0; nt < 6; nt++)
#pragma unroll
                for (int cc = 0; cc < 4; cc++) acc[nt][cc] = 0.f;

            for (int ks = 0; ks < KS; ks++) {
                const char* ba = (const char*)smem
                               + ((mt * KS + ks) * 32 + lane) * 32;
                uint4 ah = *(const uint4*)(ba + sw);
                uint4 al = *(const uint4*)(ba + (16 - sw));
                const uint4* bp = g_bofrag + (ks * NTO + ngrp * 6) * 32 + lane;
#pragma unroll
                for (int nt = 0; nt < 6; nt++) {
                    uint4 b = bp[nt * 32];
                    mma16816(acc[nt], ah, b.x, b.y);
                    mma16816(acc[nt], ah, b.z, b.w);
                    mma16816(acc[nt], al, b.x, b.y);
                }
            }
            int r0 = mt * 16 + g;
            int r1 = r0 + 8;
#pragma unroll
            for (int nt = 0; nt < 6; nt++) {
                int n = (ngrp * 6 + nt) * 8 + 2 * tig;
                float b0 = b_out[n], b1 = b_out[n + 1];
                if (r0 < PP) {
                    resT[n * RS + r0]       = acc[nt][0] + b0;
                    resT[(n + 1) * RS + r0] = acc[nt][1] + b1;
                }
                if (r1 < PP) {
                    resT[n * RS + r1]       = acc[nt][2] + b0;
                    resT[(n + 1) * RS + r1] = acc[nt][3] + b1;
                }
            }
        }
    }
    __syncthreads();

    // ---- phase 6: window-reverse, coalesced write ----
    float* obase = out + (size_t)batch * C * HH * WW
                       + (size_t)(wy * P) * WW + (wx * P);
    for (int i = tid; i < PP * C; i += NT) {
        int t  = i % PP;
        int ch = i / PP;
        int pi = t / P, pj = t % P;
        obase[((size_t)ch * HH + pi) * WW + pj] = resT[ch * RS + t];
    }
}

// ---------------------------------------------------------------------------
extern "C" void kernel_launch(void* const* d_in, const int* in_sizes, int n_in,
                              void* d_out, int out_size) {
    const float* x       = (const float*)d_in[0];
    const float* w_qkv   = (const float*)d_in[1];
    const float* b_qkv   = (const float*)d_in[2];
    const float* rel_pos = (const float*)d_in[3];
    const float* w_out   = (const float*)d_in[4];
    const float* b_out   = (const float*)d_in[5];
    float* out           = (float*)d_out;

    prep_kernel<<<96, 256>>>(w_qkv, w_out, rel_pos);

    cudaFuncSetAttribute(win_attn_kernel,
                         cudaFuncAttributeMaxDynamicSharedMemorySize,
                         SMEM_BYTES);
    win_attn_kernel<<<BATCH * NW, NT, SMEM_BYTES>>>(x, b_qkv, b_out, out);
}

// round 12
// speedup vs baseline: 3.5714x; 1.2554x over previous
#include <cuda_runtime.h>
#include <cuda_bf16.h>
#include <cstdint>

// Problem constants
#define BATCH 8
#define C     192
#define HH    224
#define WW    224
#define P     7
#define PP    49
#define NH    6
#define HD    32
#define NWX   32
#define NW    1024
#define C3    576
#define NT    576
#define RS    49          // resT stride (floats)
#define KS    12          // k-steps of 16 (K=192)
#define NTL   72          // qkv n-tiles of 8 (N=576)
#define NTO   24          // out-proj n-tiles of 8 (N=192)

// smem byte offsets
#define AFRAG_B 0          // x-frags / attn-out frags: 4mt x 12ks x 32lane x 32B = 49152
#define QOFF_B  49152      // Q A-frags: 6h x 4mt x 2ks x 32 x 32B = 49152
#define KOFF_B  98304      // K B-frags: 6h x 2ks x 7ntk x 512B    = 43008
#define VOFF_B  141312     // V B-frags: 6h x 4kp x 4ntv x 512B    = 49152
#define SMEM_BYTES 190464

// Prep scratch
__device__ uint4  g_bfrag[KS * NTL * 32];   // qkv  B frags {b0h,b1h,b0l,b1l}
__device__ uint4  g_bofrag[KS * NTO * 32];  // wout B frags
__device__ float4 g_biasfrag[NH * 4 * 7 * 32];  // bias in C-frag layout

// ---------------------------------------------------------------------------
__device__ __forceinline__ uint32_t pk_bf16x2(float a, float b) {
    __nv_bfloat16 ba = __float2bfloat16(a);
    __nv_bfloat16 bb = __float2bfloat16(b);
    return ((uint32_t)__bfloat16_as_ushort(bb) << 16) | __bfloat16_as_ushort(ba);
}
__device__ __forceinline__ float bfr(float v) {
    return __bfloat162float(__float2bfloat16(v));
}

__global__ void prep_kernel(const float* __restrict__ w_qkv,
                            const float* __restrict__ w_out,
                            const float* __restrict__ rel_pos) {
    int tid = blockIdx.x * blockDim.x + threadIdx.x;
    int stride = gridDim.x * blockDim.x;
    for (int i = tid; i < KS * NTL * 32; i += stride) {
        int ks   = i / (NTL * 32);
        int rem  = i % (NTL * 32);
        int nt   = rem / 32;
        int lane = rem % 32;
        int g = lane >> 2, tig = lane & 3;
        int n  = nt * 8 + g;
        int k0 = ks * 16 + 2 * tig;
        float v00 = w_qkv[n * C + k0],     v01 = w_qkv[n * C + k0 + 1];
        float v10 = w_qkv[n * C + k0 + 8], v11 = w_qkv[n * C + k0 + 9];
        float h00 = bfr(v00), h01 = bfr(v01), h10 = bfr(v10), h11 = bfr(v11);
        uint4 r;
        r.x = pk_bf16x2(h00, h01);
        r.y = pk_bf16x2(h10, h11);
        r.z = pk_bf16x2(v00 - h00, v01 - h01);
        r.w = pk_bf16x2(v10 - h10, v11 - h11);
        g_bfrag[i] = r;
    }
    for (int i = tid; i < KS * NTO * 32; i += stride) {
        int ks   = i / (NTO * 32);
        int rem  = i % (NTO * 32);
        int nt   = rem / 32;
        int lane = rem % 32;
        int g = lane >> 2, tig = lane & 3;
        int n  = nt * 8 + g;
        int k0 = ks * 16 + 2 * tig;
        float v00 = w_out[n * C + k0],     v01 = w_out[n * C + k0 + 1];
        float v10 = w_out[n * C + k0 + 8], v11 = w_out[n * C + k0 + 9];
        float h00 = bfr(v00), h01 = bfr(v01), h10 = bfr(v10), h11 = bfr(v11);
        uint4 r;
        r.x = pk_bf16x2(h00, h01);
        r.y = pk_bf16x2(h10, h11);
        r.z = pk_bf16x2(v00 - h00, v01 - h01);
        r.w = pk_bf16x2(v10 - h10, v11 - h11);
        g_bofrag[i] = r;
    }
    // bias in accumulator-fragment layout: [h][mti][ntk][lane] float4
    for (int i = tid; i < NH * 4 * 7 * 32; i += stride) {
        int lane = i & 31;
        int ntk  = (i >> 5) % 7;
        int mti  = (i / (32 * 7)) % 4;
        int h    = i / (32 * 7 * 4);
        int g = lane >> 2, tg = lane & 3;
        int p0 = mti * 16 + g, p1 = p0 + 8;
        int q0 = ntk * 8 + 2 * tg, q1 = q0 + 1;
        if (p0 > 48) p0 = 48;
        if (p1 > 48) p1 = 48;
        if (q0 > 48) q0 = 48;
        if (q1 > 48) q1 = 48;
        float4 r;
        {
            int ri = (p0 / 7) - (q0 / 7) + 6, rj = (p0 % 7) - (q0 % 7) + 6;
            r.x = rel_pos[(h * 13 + ri) * 13 + rj];
        }
        {
            int ri = (p0 / 7) - (q1 / 7) + 6, rj = (p0 % 7) - (q1 % 7) + 6;
            r.y = rel_pos[(h * 13 + ri) * 13 + rj];
        }
        {
            int ri = (p1 / 7) - (q0 / 7) + 6, rj = (p1 % 7) - (q0 % 7) + 6;
            r.z = rel_pos[(h * 13 + ri) * 13 + rj];
        }
        {
            int ri = (p1 / 7) - (q1 / 7) + 6, rj = (p1 % 7) - (q1 % 7) + 6;
            r.w = rel_pos[(h * 13 + ri) * 13 + rj];
        }
        g_biasfrag[i] = r;
    }
}

// bf16 mma m16n8k16, fp32 accumulate
__device__ __forceinline__ void mma16816(float c[4], uint4 a,
                                         uint32_t b0, uint32_t b1) {
    asm("mma.sync.aligned.m16n8k16.row.col.f32.bf16.bf16.f32 "
        "{%0,%1,%2,%3}, {%4,%5,%6,%7}, {%8,%9}, {%0,%1,%2,%3};"
        : "+f"(c[0]), "+f"(c[1]), "+f"(c[2]), "+f"(c[3])
        : "r"(a.x), "r"(a.y), "r"(a.z), "r"(a.w), "r"(b0), "r"(b1));
}

// ---------------------------------------------------------------------------
__global__ void __launch_bounds__(NT, 1)
win_attn_kernel(const float* __restrict__ x,
                const float* __restrict__ b_qkv,
                const float* __restrict__ b_out,
                float* __restrict__ out) {
    extern __shared__ float smem[];
    char* smc = (char*)smem;

    const int bx    = blockIdx.x;
    const int batch = bx / NW;
    const int win   = bx % NW;
    const int wy    = win / NWX;
    const int wx    = win % NWX;
    const int tid   = threadIdx.x;
    const int w     = tid >> 5;
    const int lane  = tid & 31;
    const int g     = lane >> 2, tig = lane & 3;
    const int sw    = (lane & 4) ? 16 : 0;

    // ---- phase 1: load window -> bf16 hi/lo A-fragments (zero-pad t>=49) ----
    const float* xbase = x + (size_t)batch * C * HH * WW
                           + (size_t)(wy * P) * WW + (wx * P);
    for (int i = tid; i < 96 * 64; i += NT) {
        int t  = i & 63;
        int cp = i >> 6;
        int ch = cp * 2;
        float v0 = 0.f, v1 = 0.f;
        if (t < PP) {
            const float* px = xbase + ((size_t)(t / 7)) * WW + (t % 7);
            v0 = px[(size_t)ch * HH * WW];
            v1 = px[(size_t)(ch + 1) * HH * WW];
        }
        float h0 = bfr(v0), h1 = bfr(v1);
        uint32_t hw = pk_bf16x2(h0, h1);
        uint32_t lw = pk_bf16x2(v0 - h0, v1 - h1);
        int mt = t >> 4, r = t & 15;
        int ks = ch >> 4, c = ch & 15;
        int reg   = ((r >> 3) & 1) + ((c >> 3) << 1);
        int lanep = (r & 7) * 4 + ((c & 7) >> 1);
        int swp   = (lanep & 4) ? 16 : 0;
        char* base = smc + (((mt * KS + ks) * 32 + lanep) << 5);
        *(uint32_t*)(base + swp + reg * 4)        = hw;
        *(uint32_t*)(base + (16 - swp) + reg * 4) = lw;
    }
    __syncthreads();

    // ---- phase 2: QKV GEMM on tensor cores; epilogue -> Q/K/V fragments ----
    for (int mtp = 0; mtp < 2; mtp++) {
        float acc[2][4][4];
#pragma unroll
        for (int a = 0; a < 2; a++)
#pragma unroll
            for (int b = 0; b < 4; b++)
#pragma unroll
                for (int cc = 0; cc < 4; cc++) acc[a][b][cc] = 0.f;

        for (int ks = 0; ks < KS; ks++) {
            const char* baA = smc + ((((2 * mtp) * KS + ks) * 32 + lane) << 5);
            const char* baB = baA + KS * 32 * 32;
            uint4 ahA = *(const uint4*)(baA + sw);
            uint4 alA = *(const uint4*)(baA + (16 - sw));
            uint4 ahB = *(const uint4*)(baB + sw);
            uint4 alB = *(const uint4*)(baB + (16 - sw));
            const uint4* bp = g_bfrag + (ks * NTL + w * 4) * 32 + lane;
#pragma unroll
            for (int nt = 0; nt < 4; nt++) {
                uint4 b = bp[nt * 32];
                mma16816(acc[0][nt], ahA, b.x, b.y);
                mma16816(acc[0][nt], ahA, b.z, b.w);
                mma16816(acc[0][nt], alA, b.x, b.y);
                mma16816(acc[1][nt], ahB, b.x, b.y);
                mma16816(acc[1][nt], ahB, b.z, b.w);
                mma16816(acc[1][nt], alB, b.x, b.y);
            }
        }
        // epilogue: scatter into fragment smem (warp-uniform branch by w)
#pragma unroll
        for (int a = 0; a < 2; a++) {
            const int mti = mtp * 2 + a;
#pragma unroll
            for (int nt = 0; nt < 4; nt++) {
                int n = (w * 4 + nt) * 8 + 2 * tig;
                float b0 = b_qkv[n], b1 = b_qkv[n + 1];
                float v0 = acc[a][nt][0] + b0;
                float v1 = acc[a][nt][1] + b1;
                float v2 = acc[a][nt][2] + b0;
                float v3 = acc[a][nt][3] + b1;
                if (w < 6) {                       // Q -> A-frag
                    int d = n & 31, h2 = n >> 5;
                    int ks2 = d >> 4, cc = d & 15;
                    int lanep = g * 4 + ((cc & 7) >> 1);
                    int swp = (lanep & 4) ? 16 : 0;
                    char* base = smc + QOFF_B
                               + ((((h2 * 4 + mti) * 2 + ks2) * 32 + lanep) << 5);
                    int reg = (cc >> 3) << 1;
                    float e0 = bfr(v0), e1 = bfr(v1);
                    *(uint32_t*)(base + swp + reg * 4)        = pk_bf16x2(e0, e1);
                    *(uint32_t*)(base + (16 - swp) + reg * 4) = pk_bf16x2(v0 - e0, v1 - e1);
                    float e2 = bfr(v2), e3 = bfr(v3);
                    *(uint32_t*)(base + swp + (reg + 1) * 4)        = pk_bf16x2(e2, e3);
                    *(uint32_t*)(base + (16 - swp) + (reg + 1) * 4) = pk_bf16x2(v2 - e2, v3 - e3);
                } else if (w < 12) {               // K -> B-frag
                    int d = n - 192, h2 = d >> 5, dd = d & 31;
                    int ks2 = dd >> 4, cc = dd & 15;
                    int lanep = g * 4 + ((cc & 7) >> 1);
                    int regb = cc >> 3;
                    char* cell0 = smc + KOFF_B
                                + (((h2 * 2 + ks2) * 7 + mti * 2) << 9)
                                + lanep * 8 + regb * 4;
                    float e0 = bfr(v0), e1 = bfr(v1);
                    *(uint32_t*)(cell0)       = pk_bf16x2(e0, e1);
                    *(uint32_t*)(cell0 + 256) = pk_bf16x2(v0 - e0, v1 - e1);
                    if (mti < 3) {                 // keys >= 56 have no cell
                        char* cell1 = cell0 + 512;
                        float e2 = bfr(v2), e3 = bfr(v3);
                        *(uint32_t*)(cell1)       = pk_bf16x2(e2, e3);
                        *(uint32_t*)(cell1 + 256) = pk_bf16x2(v2 - e2, v3 - e3);
                    }
                } else {                           // V -> B-frag (16-bit stores)
                    int d = n - 384, h2 = d >> 5, dd = d & 31;
                    int ntv = dd >> 3, gc = dd & 7;
                    char* cb = smc + VOFF_B + (((h2 * 4 + mti) * 4 + ntv) << 9);
                    int l0 = gc * 4 + (g >> 1);
                    int ho = (g & 1) * 2;
                    char* p00 = cb + l0 * 8 + ho;          // key g,   dim gc
                    char* p10 = cb + (l0 + 4) * 8 + ho;    // key g,   dim gc+1
                    float e;
                    e = bfr(v0);
                    *(__nv_bfloat16*)(p00)       = __float2bfloat16(e);
                    *(__nv_bfloat16*)(p00 + 256) = __float2bfloat16(v0 - e);
                    e = bfr(v1);
                    *(__nv_bfloat16*)(p10)       = __float2bfloat16(e);
                    *(__nv_bfloat16*)(p10 + 256) = __float2bfloat16(v1 - e);
                    e = bfr(v2);                           // key g+8 -> word+4
                    *(__nv_bfloat16*)(p00 + 4)       = __float2bfloat16(e);
                    *(__nv_bfloat16*)(p00 + 4 + 256) = __float2bfloat16(v2 - e);
                    e = bfr(v3);
                    *(__nv_bfloat16*)(p10 + 4)       = __float2bfloat16(e);
                    *(__nv_bfloat16*)(p10 + 4 + 256) = __float2bfloat16(v3 - e);
                }
            }
        }
    }
    __syncthreads();

    // ---- phase 3: attention on tensor cores. warp = (head, row-half) ----
    if (w < 12) {
        const int h  = w >> 1;
        const int mh = w & 1;
        const float scale = 0.1767766952966369f;
        for (int m2 = 0; m2 < 2; m2++) {
            const int mti = mh * 2 + m2;
            uint4 qh[2], ql[2];
#pragma unroll
            for (int ks2 = 0; ks2 < 2; ks2++) {
                const char* qb = smc + QOFF_B
                               + ((((h * 4 + mti) * 2 + ks2) * 32 + lane) << 5);
                qh[ks2] = *(const uint4*)(qb + sw);
                ql[ks2] = *(const uint4*)(qb + (16 - sw));
            }
            float s[7][4];
#pragma unroll
            for (int ntk = 0; ntk < 7; ntk++)
#pragma unroll
                for (int cc = 0; cc < 4; cc++) s[ntk][cc] = 0.f;
#pragma unroll
            for (int ks2 = 0; ks2 < 2; ks2++) {
                const char* kb = smc + KOFF_B + (((h * 2 + ks2) * 7) << 9) + lane * 8;
#pragma unroll
                for (int ntk = 0; ntk < 7; ntk++) {
                    uint2 kh = *(const uint2*)(kb + ntk * 512);
                    uint2 kl = *(const uint2*)(kb + ntk * 512 + 256);
                    mma16816(s[ntk], qh[ks2], kh.x, kh.y);
                    mma16816(s[ntk], qh[ks2], kl.x, kl.y);
                    mma16816(s[ntk], ql[ks2], kh.x, kh.y);
                }
            }
            // scale + bias + key mask
            const float4* bfp = g_biasfrag + ((h * 4 + mti) * 7) * 32 + lane;
#pragma unroll
            for (int ntk = 0; ntk < 7; ntk++) {
                float4 bb = bfp[ntk * 32];
                s[ntk][0] = s[ntk][0] * scale + bb.x;
                s[ntk][1] = s[ntk][1] * scale + bb.y;
                s[ntk][2] = s[ntk][2] * scale + bb.z;
                s[ntk][3] = s[ntk][3] * scale + bb.w;
            }
            if (tig != 0) { s[6][0] = -1e30f; s[6][2] = -1e30f; }
            s[6][1] = -1e30f; s[6][3] = -1e30f;
            // softmax (rows g and g+8), reduce over tig group
            float mxa = -1e30f, mxb = -1e30f;
#pragma unroll
            for (int ntk = 0; ntk < 7; ntk++) {
                mxa = fmaxf(mxa, fmaxf(s[ntk][0], s[ntk][1]));
                mxb = fmaxf(mxb, fmaxf(s[ntk][2], s[ntk][3]));
            }
            mxa = fmaxf(mxa, __shfl_xor_sync(0xffffffffu, mxa, 1));
            mxa = fmaxf(mxa, __shfl_xor_sync(0xffffffffu, mxa, 2));
            mxb = fmaxf(mxb, __shfl_xor_sync(0xffffffffu, mxb, 1));
            mxb = fmaxf(mxb, __shfl_xor_sync(0xffffffffu, mxb, 2));
            float sa = 0.f, sb = 0.f;
#pragma unroll
            for (int ntk = 0; ntk < 7; ntk++) {
                s[ntk][0] = __expf(s[ntk][0] - mxa); sa += s[ntk][0];
                s[ntk][1] = __expf(s[ntk][1] - mxa); sa += s[ntk][1];
                s[ntk][2] = __expf(s[ntk][2] - mxb); sb += s[ntk][2];
                s[ntk][3] = __expf(s[ntk][3] - mxb); sb += s[ntk][3];
            }
            sa += __shfl_xor_sync(0xffffffffu, sa, 1);
            sa += __shfl_xor_sync(0xffffffffu, sa, 2);
            sb += __shfl_xor_sync(0xffffffffu, sb, 1);
            sb += __shfl_xor_sync(0xffffffffu, sb, 2);
            float inva = 1.f / sa, invb = 1.f / sb;
#pragma unroll
            for (int ntk = 0; ntk < 7; ntk++) {
                s[ntk][0] *= inva; s[ntk][1] *= inva;
                s[ntk][2] *= invb; s[ntk][3] *= invb;
            }
            // PV: P accumulator layout == A-frag layout for n-tile pairs
            float o[4][4];
#pragma unroll
            for (int ntv = 0; ntv < 4; ntv++)
#pragma unroll
                for (int cc = 0; cc < 4; cc++) o[ntv][cc] = 0.f;
#pragma unroll
            for (int kp = 0; kp < 4; kp++) {
                float p00 = s[2 * kp][0], p01 = s[2 * kp][1];
                float p10 = s[2 * kp][2], p11 = s[2 * kp][3];
                float q00 = 0.f, q01 = 0.f, q10 = 0.f, q11 = 0.f;
                if (kp < 3) {
                    q00 = s[2 * kp + 1][0]; q01 = s[2 * kp + 1][1];
                    q10 = s[2 * kp + 1][2]; q11 = s[2 * kp + 1][3];
                }
                float e00 = bfr(p00), e01 = bfr(p01), e10 = bfr(p10), e11 = bfr(p11);
                float f00 = bfr(q00), f01 = bfr(q01), f10 = bfr(q10), f11 = bfr(q11);
                uint4 ph, pl;
                ph.x = pk_bf16x2(e00, e01); pl.x = pk_bf16x2(p00 - e00, p01 - e01);
                ph.y = pk_bf16x2(e10, e11); pl.y = pk_bf16x2(p10 - e10, p11 - e11);
                ph.z = pk_bf16x2(f00, f01); pl.z = pk_bf16x2(q00 - f00, q01 - f01);
                ph.w = pk_bf16x2(f10, f11); pl.w = pk_bf16x2(q10 - f10, q11 - f11);
                const char* vb = smc + VOFF_B + (((h * 4 + kp) * 4) << 9) + lane * 8;
#pragma unroll
                for (int ntv = 0; ntv < 4; ntv++) {
                    uint2 vh = *(const uint2*)(vb + ntv * 512);
                    uint2 vl = *(const uint2*)(vb + ntv * 512 + 256);
                    mma16816(o[ntv], ph, vh.x, vh.y);
                    mma16816(o[ntv], ph, vl.x, vl.y);
                    mma16816(o[ntv], pl, vh.x, vh.y);
                }
            }
            // epilogue: O -> attn-out A-frags (region A)
#pragma unroll
            for (int ntv = 0; ntv < 4; ntv++) {
                int dd  = ntv * 8 + 2 * tig;
                int cch = h * 32 + dd;
                int ksx = cch >> 4, cc = cch & 15;
                int lanep = g * 4 + ((cc & 7) >> 1);
                int swp = (lanep & 4) ? 16 : 0;
                char* base = smc + (((mti * KS + ksx) * 32 + lanep) << 5);
                int reg = (cc >> 3) << 1;
                float v0 = o[ntv][0], v1 = o[ntv][1];
                float v2 = o[ntv][2], v3 = o[ntv][3];
                float e0 = bfr(v0), e1 = bfr(v1);
                *(uint32_t*)(base + swp + reg * 4)        = pk_bf16x2(e0, e1);
                *(uint32_t*)(base + (16 - swp) + reg * 4) = pk_bf16x2(v0 - e0, v1 - e1);
                float e2 = bfr(v2), e3 = bfr(v3);
                *(uint32_t*)(base + swp + (reg + 1) * 4)        = pk_bf16x2(e2, e3);
                *(uint32_t*)(base + (16 - swp) + (reg + 1) * 4) = pk_bf16x2(v2 - e2, v3 - e3);
            }
        }
    }
    __syncthreads();

    // ---- phase 5: output projection on tensor cores ----
    float* resT = (float*)(smc + QOFF_B);   // [ch][t] stride RS (Q frags dead)
    {
        if (w < 16) {
            const int mt   = w >> 2;
            const int ngrp = w & 3;
            float acc[6][4];
#pragma unroll
            for (int nt = 0; nt < 6; nt++)
#pragma unroll
                for (int cc = 0; cc < 4; cc++) acc[nt][cc] = 0.f;

            for (int ks = 0; ks < KS; ks++) {
                const char* ba = smc + (((mt * KS + ks) * 32 + lane) << 5);
                uint4 ah = *(const uint4*)(ba + sw);
                uint4 al = *(const uint4*)(ba + (16 - sw));
                const uint4* bp = g_bofrag + (ks * NTO + ngrp * 6) * 32 + lane;
#pragma unroll
                for (int nt = 0; nt < 6; nt++) {
                    uint4 b = bp[nt * 32];
                    mma16816(acc[nt], ah, b.x, b.y);
                    mma16816(acc[nt], ah, b.z, b.w);
                    mma16816(acc[nt], al, b.x, b.y);
                }
            }
            int r0 = mt * 16 + g;
            int r1 = r0 + 8;
#pragma unroll
            for (int nt = 0; nt < 6; nt++) {
                int n = (ngrp * 6 + nt) * 8 + 2 * tig;
                float b0 = b_out[n], b1 = b_out[n + 1];
                if (r0 < PP) {
                    resT[n * RS + r0]       = acc[nt][0] + b0;
                    resT[(n + 1) * RS + r0] = acc[nt][1] + b1;
                }
                if (r1 < PP) {
                    resT[n * RS + r1]       = acc[nt][2] + b0;
                    resT[(n + 1) * RS + r1] = acc[nt][3] + b1;
                }
            }
        }
    }
    __syncthreads();

    // ---- phase 6: window-reverse, coalesced write ----
    float* obase = out + (size_t)batch * C * HH * WW
                       + (size_t)(wy * P) * WW + (wx * P);
    for (int i = tid; i < PP * C; i += NT) {
        int t  = i % PP;
        int ch = i / PP;
        int pi = t / P, pj = t % P;
        obase[((size_t)ch * HH + pi) * WW + pj] = resT[ch * RS + t];
    }
}

// ---------------------------------------------------------------------------
extern "C" void kernel_launch(void* const* d_in, const int* in_sizes, int n_in,
                              void* d_out, int out_size) {
    const float* x       = (const float*)d_in[0];
    const float* w_qkv   = (const float*)d_in[1];
    const float* b_qkv   = (const float*)d_in[2];
    const float* rel_pos = (const float*)d_in[3];
    const float* w_out   = (const float*)d_in[4];
    const float* b_out   = (const float*)d_in[5];
    float* out           = (float*)d_out;

    prep_kernel<<<96, 256>>>(w_qkv, w_out, rel_pos);

    cudaFuncSetAttribute(win_attn_kernel,
                         cudaFuncAttributeMaxDynamicSharedMemorySize,
                         SMEM_BYTES);
    win_attn_kernel<<<BATCH * NW, NT, SMEM_BYTES>>>(x, b_qkv, b_out, out);
}